// round 3
// baseline (speedup 1.0000x reference)
#include <cuda_runtime.h>
#include <math.h>

#define SQ   2048
#define DIM  1024
#define NH   16
#define HDIM 64
#define NELEM (NH * SQ * HDIM)   // 2,097,152 floats per [H,S,HD] tensor

// Scratch: QG, KG, VG, QL, KL, VL, AO  (7 x 8MB = 56MB)
__device__ float g_scratch[7 * NELEM];

// ---------------------------------------------------------------------------
// 128x64-tile fp32 GEMM, 256 threads, 8x4 per-thread microtile.
//   C_blk[m,e] = sum_k A[m0+m, k] * B_blk[k, e]
//   grid.x = M/128 tiles, grid.y = N-block index (head or 64-col block)
//   B_blk = B + blockIdx.y * bStride, C_blk = C + blockIdx.y * cStride
// Used for:
//   projections: A=[S,D] lda=D, B=W+h*D*HD ldb=HD bStride=D*HD,
//                C=[H,S,HD] ldc=HD cStride=S*HD
//   out-proj:    A=[S,1024] lda=1024, B=Wo ldb=1024 bStride=64,
//                C=out ldc=1024 cStride=64
// ---------------------------------------------------------------------------
__global__ __launch_bounds__(256)
void gemm128_kernel(const float* __restrict__ A, int lda,
                    const float* __restrict__ B, int ldb, long bStride,
                    float* __restrict__ C, int ldc, long cStride,
                    int Kdim) {
    __shared__ float As[16][128];   // As[k][m]
    __shared__ float Bs[16][64];    // Bs[k][e]

    const int m0 = blockIdx.x * 128;
    const float* Bblk = B + (long)blockIdx.y * bStride;
    float*       Cblk = C + (long)blockIdx.y * cStride;

    const int tid = threadIdx.x;
    const int tx = tid & 15;     // 0..15 -> 4 output cols each
    const int ty = tid >> 4;     // 0..15 -> 8 output rows each

    float acc[8][4] = {};

    for (int k0 = 0; k0 < Kdim; k0 += 16) {
        // Load A tile: 128 m x 16 k = 512 float4 tasks (transpose into As[k][m])
        #pragma unroll
        for (int it = 0; it < 2; it++) {
            int task = tid + it * 256;          // 0..511
            int m  = task & 127;
            int k4 = (task >> 7) * 4;           // 0,4,8,12
            float4 v = *reinterpret_cast<const float4*>(
                &A[(long)(m0 + m) * lda + k0 + k4]);
            As[k4 + 0][m] = v.x;
            As[k4 + 1][m] = v.y;
            As[k4 + 2][m] = v.z;
            As[k4 + 3][m] = v.w;
        }
        // Load B tile: 16 k x 64 e = 256 float4 tasks
        {
            int k  = tid >> 4;
            int e4 = (tid & 15) * 4;
            *reinterpret_cast<float4*>(&Bs[k][e4]) =
                *reinterpret_cast<const float4*>(&Bblk[(long)(k0 + k) * ldb + e4]);
        }
        __syncthreads();

        #pragma unroll
        for (int k = 0; k < 16; k++) {
            float4 a0 = *reinterpret_cast<const float4*>(&As[k][ty * 8]);
            float4 a1 = *reinterpret_cast<const float4*>(&As[k][ty * 8 + 4]);
            float4 b4 = *reinterpret_cast<const float4*>(&Bs[k][tx * 4]);
            float av[8] = {a0.x, a0.y, a0.z, a0.w, a1.x, a1.y, a1.z, a1.w};
            float bv[4] = {b4.x, b4.y, b4.z, b4.w};
            #pragma unroll
            for (int i = 0; i < 8; i++)
                #pragma unroll
                for (int j = 0; j < 4; j++)
                    acc[i][j] = fmaf(av[i], bv[j], acc[i][j]);
        }
        __syncthreads();
    }

    #pragma unroll
    for (int i = 0; i < 8; i++) {
        float4 v = make_float4(acc[i][0], acc[i][1], acc[i][2], acc[i][3]);
        *reinterpret_cast<float4*>(
            &Cblk[(long)(m0 + ty * 8 + i) * ldc + tx * 4]) = v;
    }
}

// ---------------------------------------------------------------------------
// Flash attention (fp32, online softmax). One block per (head, 128-row q tile),
// 512 threads, 4x4 microtile. Q,K,V layout [H,S,HD]; O layout [H,S,HD]
// (== the reference's raw .reshape view, no head transpose).
// ---------------------------------------------------------------------------
#define PAD 68   // row stride in floats: 272B = 16B aligned, conflict-light
// Qs(128) + Ks(64) + Vs(64) + Ps(128) rows of PAD floats
#define SMEMA ((128 + 64 + 64 + 128) * PAD * 4)   // 104448 bytes

__global__ __launch_bounds__(512)
void attn_kernel(const float* __restrict__ Q, const float* __restrict__ K,
                 const float* __restrict__ V, float* __restrict__ O) {
    extern __shared__ float sm[];
    float* Qs = sm;                        // 128 x PAD
    float* Ks = sm + 128 * PAD;            // 64 x PAD
    float* Vs = sm + (128 + 64) * PAD;     // 64 x PAD
    float* Ps = sm + (128 + 128) * PAD;    // 128 x PAD

    const int h  = blockIdx.y;
    const int q0 = blockIdx.x * 128;
    const float* Qh = Q + (long)h * SQ * HDIM;
    const float* Kh = K + (long)h * SQ * HDIM;
    const float* Vh = V + (long)h * SQ * HDIM;

    const int tid = threadIdx.x;
    const int tx = tid & 15;   // k-cols (S phase) / e-cols (PV phase)
    const int ty = tid >> 4;   // 0..31 -> 4 q-rows each

    // Load Q tile (128 x 64 floats = 2048 float4)
    #pragma unroll
    for (int it = 0; it < 4; it++) {
        int task = tid + it * 512;
        int r = task >> 4, c4 = (task & 15) * 4;
        *reinterpret_cast<float4*>(&Qs[r * PAD + c4]) =
            *reinterpret_cast<const float4*>(&Qh[(long)(q0 + r) * HDIM + c4]);
    }

    float m_i[4], l_i[4], acc[4][4];
    #pragma unroll
    for (int i = 0; i < 4; i++) {
        m_i[i] = -1e30f;
        l_i[i] = 0.f;
        #pragma unroll
        for (int j = 0; j < 4; j++) acc[i][j] = 0.f;
    }
    const float scale = 0.125f;   // 1/sqrt(64)

    for (int j0 = 0; j0 < SQ; j0 += 64) {
        __syncthreads();   // prev-iter readers of Ks/Vs/Ps are done (also fences Qs load on iter 0 via 2nd sync)
        // Load K and V tiles (64 x 64 each = 1024 float4 each)
        #pragma unroll
        for (int it = 0; it < 2; it++) {
            int task = tid + it * 512;
            int r = task >> 4, c4 = (task & 15) * 4;
            *reinterpret_cast<float4*>(&Ks[r * PAD + c4]) =
                *reinterpret_cast<const float4*>(&Kh[(long)(j0 + r) * HDIM + c4]);
            *reinterpret_cast<float4*>(&Vs[r * PAD + c4]) =
                *reinterpret_cast<const float4*>(&Vh[(long)(j0 + r) * HDIM + c4]);
        }
        __syncthreads();

        // S tile: sv[i][j] = Q[q0+ty*4+i] . K[j0+tx*4+j]
        float sv[4][4] = {};
        #pragma unroll
        for (int e0 = 0; e0 < 64; e0 += 4) {
            float4 qa[4], kb[4];
            #pragma unroll
            for (int i = 0; i < 4; i++)
                qa[i] = *reinterpret_cast<const float4*>(&Qs[(ty * 4 + i) * PAD + e0]);
            #pragma unroll
            for (int j = 0; j < 4; j++)
                kb[j] = *reinterpret_cast<const float4*>(&Ks[(tx * 4 + j) * PAD + e0]);
            #pragma unroll
            for (int i = 0; i < 4; i++)
                #pragma unroll
                for (int j = 0; j < 4; j++)
                    sv[i][j] += qa[i].x * kb[j].x + qa[i].y * kb[j].y +
                                qa[i].z * kb[j].z + qa[i].w * kb[j].w;
        }

        // Online softmax per q row (reduce across the 16 tx lanes; lanes 0-15 /
        // 16-31 of a warp each share one ty, so width-16 shfl groups are exact)
        #pragma unroll
        for (int i = 0; i < 4; i++) {
            float mx = sv[i][0];
            #pragma unroll
            for (int j = 1; j < 4; j++) mx = fmaxf(mx, sv[i][j]);
            #pragma unroll
            for (int off = 8; off > 0; off >>= 1)
                mx = fmaxf(mx, __shfl_xor_sync(0xffffffffu, mx, off, 16));
            float newm = fmaxf(m_i[i], mx * scale);
            float corr = __expf(m_i[i] - newm);
            m_i[i] = newm;

            float p[4], rsum = 0.f;
            #pragma unroll
            for (int j = 0; j < 4; j++) {
                p[j] = __expf(sv[i][j] * scale - newm);
                rsum += p[j];
            }
            *reinterpret_cast<float4*>(&Ps[(ty * 4 + i) * PAD + tx * 4]) =
                make_float4(p[0], p[1], p[2], p[3]);
            #pragma unroll
            for (int off = 8; off > 0; off >>= 1)
                rsum += __shfl_xor_sync(0xffffffffu, rsum, off, 16);
            l_i[i] = l_i[i] * corr + rsum;
            #pragma unroll
            for (int j = 0; j < 4; j++) acc[i][j] *= corr;
        }
        __syncthreads();

        // acc += P @ V  (acc[i][j]: q-row ty*4+i, e-col tx*4+j)
        #pragma unroll
        for (int k0 = 0; k0 < 64; k0 += 4) {
            float4 pa[4], vb[4];
            #pragma unroll
            for (int i = 0; i < 4; i++)
                pa[i] = *reinterpret_cast<const float4*>(&Ps[(ty * 4 + i) * PAD + k0]);
            #pragma unroll
            for (int kk = 0; kk < 4; kk++)
                vb[kk] = *reinterpret_cast<const float4*>(&Vs[(k0 + kk) * PAD + tx * 4]);
            #pragma unroll
            for (int i = 0; i < 4; i++) {
                acc[i][0] += pa[i].x * vb[0].x + pa[i].y * vb[1].x + pa[i].z * vb[2].x + pa[i].w * vb[3].x;
                acc[i][1] += pa[i].x * vb[0].y + pa[i].y * vb[1].y + pa[i].z * vb[2].y + pa[i].w * vb[3].y;
                acc[i][2] += pa[i].x * vb[0].z + pa[i].y * vb[1].z + pa[i].z * vb[2].z + pa[i].w * vb[3].z;
                acc[i][3] += pa[i].x * vb[0].w + pa[i].y * vb[1].w + pa[i].z * vb[2].w + pa[i].w * vb[3].w;
            }
        }
    }

    // Epilogue: normalize and store. O is [H, S, HD] contiguous — identical
    // memory layout to the reference's raw reshape to [S, H*HD].
    #pragma unroll
    for (int i = 0; i < 4; i++) {
        float inv = 1.0f / l_i[i];
        float4 v = make_float4(acc[i][0] * inv, acc[i][1] * inv,
                               acc[i][2] * inv, acc[i][3] * inv);
        *reinterpret_cast<float4*>(
            &O[(long)h * SQ * HDIM + (long)(q0 + ty * 4 + i) * HDIM + tx * 4]) = v;
    }
}

// ---------------------------------------------------------------------------
// Launch
// ---------------------------------------------------------------------------
extern "C" void kernel_launch(void* const* d_in, const int* in_sizes, int n_in,
                              void* d_out, int out_size) {
    const float* GLO = (const float*)d_in[0];
    const float* LOC = (const float*)d_in[1];
    const float* Wq  = (const float*)d_in[2];
    const float* Wk  = (const float*)d_in[3];
    const float* Wv  = (const float*)d_in[4];
    const float* Wo  = (const float*)d_in[5];
    float* out = (float*)d_out;

    float* scratch = nullptr;
    cudaGetSymbolAddress((void**)&scratch, g_scratch);
    float* QG = scratch + 0L * NELEM;
    float* KG = scratch + 1L * NELEM;
    float* VG = scratch + 2L * NELEM;
    float* QL = scratch + 3L * NELEM;
    float* KL = scratch + 4L * NELEM;
    float* VL = scratch + 5L * NELEM;
    float* AO = scratch + 6L * NELEM;

    cudaFuncSetAttribute(attn_kernel, cudaFuncAttributeMaxDynamicSharedMemorySize, SMEMA);

    const dim3 gproj(SQ / 128, NH);        // per-head projection tiles
    const dim3 gattn(SQ / 128, NH);
    const dim3 gout(SQ / 128, DIM / 64);   // output projection tiles
    const long wStride = (long)DIM * HDIM; // per-head weight stride
    const long cStride = (long)SQ * HDIM;  // per-head output stride

    // 6 projections -> [H, S, HD] each
    gemm128_kernel<<<gproj, 256>>>(GLO, DIM, Wq, HDIM, wStride, QG, HDIM, cStride, DIM);
    gemm128_kernel<<<gproj, 256>>>(GLO, DIM, Wk, HDIM, wStride, KG, HDIM, cStride, DIM);
    gemm128_kernel<<<gproj, 256>>>(GLO, DIM, Wv, HDIM, wStride, VG, HDIM, cStride, DIM);
    gemm128_kernel<<<gproj, 256>>>(LOC, DIM, Wq, HDIM, wStride, QL, HDIM, cStride, DIM);
    gemm128_kernel<<<gproj, 256>>>(LOC, DIM, Wk, HDIM, wStride, KL, HDIM, cStride, DIM);
    gemm128_kernel<<<gproj, 256>>>(LOC, DIM, Wv, HDIM, wStride, VL, HDIM, cStride, DIM);

    // GLO' = attn(Q=GLO, KV=LOC) @ Wo
    attn_kernel<<<gattn, 512, SMEMA>>>(QG, KL, VL, AO);
    gemm128_kernel<<<gout, 256>>>(AO, DIM, Wo, DIM, 64L, out, DIM, 64L, DIM);

    // LOC' = attn(Q=LOC, KV=GLO) @ Wo
    attn_kernel<<<gattn, 512, SMEMA>>>(QL, KG, VG, AO);
    gemm128_kernel<<<gout, 256>>>(AO, DIM, Wo, DIM, 64L, out + (long)SQ * DIM, DIM, 64L, DIM);
}

// round 5
// speedup vs baseline: 1.4107x; 1.4107x over previous
#include <cuda_runtime.h>
#include <math.h>

#define SQ   2048
#define DIM  1024
#define NH   16
#define HDIM 64
#define NELEM (NH * SQ * HDIM)   // 2,097,152 floats per [H,S,HD] tensor

// Scratch slots: 0..5 = QG,KG,VG,QL,KL,VL ; 6 = AO_G ; 7 = AO_L  (8 x 8MB = 64MB)
__device__ float g_scratch[8 * NELEM];

// ---- packed f32x2 helpers (sm_103a FFMA2 path; ptxas never auto-fuses) ----
#define FMA2(d, a, b) \
    asm("fma.rn.f32x2 %0, %1, %2, %0;" : "+l"(d) : "l"(a), "l"(b))
#define MUL2(d, a, b) \
    asm("mul.rn.f32x2 %0, %1, %2;" : "=l"(d) : "l"(a), "l"(b))
#define PACK2(d, x) \
    asm("mov.b64 %0, {%1, %1};" : "=l"(d) : "f"(x))
#define UNPACK2(lo, hi, s) \
    asm("mov.b64 {%0, %1}, %2;" : "=f"(lo), "=f"(hi) : "l"(s))

// ---------------------------------------------------------------------------
// 128x64-tile fp32 GEMM body, BK=32, 256 threads, 8x4 microtile, f32x2 math.
//   C[m,e] = sum_k A[m0+m, k] * B[k, e]
// As: [128][32] plain (reads are half-warp broadcasts, stores conflict-free)
// Bs: [64][32] transposed (row = e, col = k) with 16B-chunk XOR swizzle:
//   physical chunk p = (k>>2) ^ ((e>>2)&7)  -> strided 4-row reads conflict-free
// ---------------------------------------------------------------------------
__device__ __forceinline__ void gemm128x64(
    const float* __restrict__ A, int lda,
    const float* __restrict__ B, int ldb,
    float* __restrict__ C, int ldc,
    int Kdim, int m0, float* As, float* Bs)
{
    const int tid = threadIdx.x;
    const int tx = tid & 15;     // 0..15 -> 4 e-cols each
    const int ty = tid >> 4;     // 0..15 -> 8 m-rows each

    unsigned long long acc[8][4] = {};   // f32x2 (even-k, odd-k) partial sums

    for (int k0 = 0; k0 < Kdim; k0 += 32) {
        // A tile: 128 m x 32 k = 1024 float4 tasks (plain row-major [m][k])
        #pragma unroll
        for (int it = 0; it < 4; it++) {
            int task = tid + it * 256;
            int m = task >> 3, k4 = (task & 7) * 4;
            *reinterpret_cast<float4*>(&As[m * 32 + k4]) =
                *reinterpret_cast<const float4*>(&A[(long)(m0 + m) * lda + k0 + k4]);
        }
        // B tile: 32 k x 64 e, transpose+swizzle into Bs[e][k]
        #pragma unroll
        for (int it = 0; it < 2; it++) {
            int task = tid + it * 256;
            int k = task >> 4, e4 = (task & 15) * 4;
            float4 v = *reinterpret_cast<const float4*>(&B[(long)(k0 + k) * ldb + e4]);
            int sw = (((k >> 2) ^ (task & 7)) << 2) + (k & 3);  // (e4>>2)&7 == task&7
            Bs[(e4 + 0) * 32 + sw] = v.x;
            Bs[(e4 + 1) * 32 + sw] = v.y;
            Bs[(e4 + 2) * 32 + sw] = v.z;
            Bs[(e4 + 3) * 32 + sw] = v.w;
        }
        __syncthreads();

        #pragma unroll
        for (int c = 0; c < 8; c++) {
            ulonglong2 a2[8], b2[4];
            #pragma unroll
            for (int i = 0; i < 8; i++)
                a2[i] = *reinterpret_cast<const ulonglong2*>(&As[(ty * 8 + i) * 32 + c * 4]);
            const int pc = (c ^ (tx & 7)) * 4;
            #pragma unroll
            for (int j = 0; j < 4; j++)
                b2[j] = *reinterpret_cast<const ulonglong2*>(&Bs[(tx * 4 + j) * 32 + pc]);
            #pragma unroll
            for (int i = 0; i < 8; i++)
                #pragma unroll
                for (int j = 0; j < 4; j++) {
                    FMA2(acc[i][j], a2[i].x, b2[j].x);
                    FMA2(acc[i][j], a2[i].y, b2[j].y);
                }
        }
        __syncthreads();
    }

    #pragma unroll
    for (int i = 0; i < 8; i++) {
        float r[4];
        #pragma unroll
        for (int j = 0; j < 4; j++) {
            float lo, hi;
            UNPACK2(lo, hi, acc[i][j]);
            r[j] = lo + hi;
        }
        *reinterpret_cast<float4*>(&C[(long)(m0 + ty * 8 + i) * ldc + tx * 4]) =
            make_float4(r[0], r[1], r[2], r[3]);
    }
}

// All 6 projections in one launch: grid (SQ/128, NH, 6)
__global__ __launch_bounds__(256)
void proj_kernel(const float* __restrict__ GLO, const float* __restrict__ LOC,
                 const float* __restrict__ Wq, const float* __restrict__ Wk,
                 const float* __restrict__ Wv, float* __restrict__ scratch) {
    __shared__ float As[128 * 32];
    __shared__ float Bs[64 * 32];
    const int z = blockIdx.z;            // 0..5: QG,KG,VG,QL,KL,VL
    const int h = blockIdx.y;
    const int m0 = blockIdx.x * 128;
    const float* A = (z < 3) ? GLO : LOC;
    const int wsel = (z < 3) ? z : z - 3;
    const float* W = (wsel == 0) ? Wq : (wsel == 1) ? Wk : Wv;
    gemm128x64(A, DIM, W + (long)h * DIM * HDIM, HDIM,
               scratch + (long)z * NELEM + (long)h * SQ * HDIM, HDIM,
               DIM, m0, As, Bs);
}

// Both output projections in one launch: grid (SQ/128, DIM/64, 2)
// A = attention output buffer read as flat [2048,1024] (matches the
// reference's raw .reshape of the [H,S,HD] buffer — no head transpose).
__global__ __launch_bounds__(256)
void outproj_kernel(const float* __restrict__ scratch, const float* __restrict__ Wo,
                    float* __restrict__ out) {
    __shared__ float As[128 * 32];
    __shared__ float Bs[64 * 32];
    const int z = blockIdx.z;
    const int y = blockIdx.y;
    const int m0 = blockIdx.x * 128;
    gemm128x64(scratch + (long)(6 + z) * NELEM, DIM, Wo + y * 64, DIM,
               out + (long)z * SQ * DIM + y * 64, DIM, DIM, m0, As, Bs);
}

// ---------------------------------------------------------------------------
// Flash attention, f32x2. One block per (z, head, 128-row q tile), 512 thr.
// Qs[128][64], Ps[128][64]: plain (broadcast reads, conflict-free stores).
// Ks[64][64]: row-major (key,e), 16B-chunk swizzled -> conflict-free 4-row reads.
// Vt[64][64]: TRANSPOSED (row=e, col=key) + swizzled, so PV packs along key.
// ---------------------------------------------------------------------------
#define SMEMA ((128 + 64 + 64 + 128) * 64 * 4)   // 98304 bytes

__global__ __launch_bounds__(512)
void attn_kernel(const float* __restrict__ scratch, float* __restrict__ scratch_out) {
    extern __shared__ float sm[];
    float* Qs = sm;                  // 128 x 64
    float* Ks = sm + 128 * 64;       // 64 x 64 (swizzled)
    float* Vt = sm + 192 * 64;       // 64 x 64 (transposed + swizzled)
    float* Ps = sm + 256 * 64;       // 128 x 64

    const int z = blockIdx.z;
    const float* Q = scratch + (long)(z ? 3 : 0) * NELEM;  // QL : QG
    const float* K = scratch + (long)(z ? 1 : 4) * NELEM;  // KG : KL
    const float* V = scratch + (long)(z ? 2 : 5) * NELEM;  // VG : VL
    float* O = scratch_out + (long)(6 + z) * NELEM;

    const int h  = blockIdx.y;
    const int q0 = blockIdx.x * 128;
    const float* Qh = Q + (long)h * SQ * HDIM;
    const float* Kh = K + (long)h * SQ * HDIM;
    const float* Vh = V + (long)h * SQ * HDIM;

    const int tid = threadIdx.x;
    const int tx = tid & 15;   // k-cols (S phase) / e-cols (PV phase)
    const int ty = tid >> 4;   // 0..31 -> 4 q-rows each
    const int sw = tx & 7;

    // Load Q tile (128 x 64 = 2048 float4), plain layout
    #pragma unroll
    for (int it = 0; it < 4; it++) {
        int task = tid + it * 512;
        int r = task >> 4, c4 = (task & 15) * 4;
        *reinterpret_cast<float4*>(&Qs[r * 64 + c4]) =
            *reinterpret_cast<const float4*>(&Qh[(long)(q0 + r) * HDIM + c4]);
    }

    float m_i[4], l_i[4];
    unsigned long long acc[4][4] = {};
    #pragma unroll
    for (int i = 0; i < 4; i++) { m_i[i] = -1e30f; l_i[i] = 0.f; }
    const float scale = 0.125f;   // 1/sqrt(64)

    for (int j0 = 0; j0 < SQ; j0 += 64) {
        __syncthreads();   // prev-iter readers of Ks/Vt/Ps done (iter0: Qs fence via 2nd sync)
        // K: swizzled row-major; V: transposed + swizzled
        #pragma unroll
        for (int it = 0; it < 2; it++) {
            int task = tid + it * 512;
            int r = task >> 4;           // key row 0..63
            int ci = task & 15;          // 16B chunk index along e
            int c4 = ci * 4;
            *reinterpret_cast<float4*>(&Ks[r * 64 + ((ci ^ ((r >> 2) & 7)) << 2)]) =
                *reinterpret_cast<const float4*>(&Kh[(long)(j0 + r) * HDIM + c4]);
            float4 v = *reinterpret_cast<const float4*>(&Vh[(long)(j0 + r) * HDIM + c4]);
            int colp = (((r >> 2) ^ (ci & 7)) << 2) + (r & 3);  // (e-row>>2)&7 == ci&7
            Vt[(c4 + 0) * 64 + colp] = v.x;
            Vt[(c4 + 1) * 64 + colp] = v.y;
            Vt[(c4 + 2) * 64 + colp] = v.z;
            Vt[(c4 + 3) * 64 + colp] = v.w;
        }
        __syncthreads();

        // S tile (packed over e): sv2[i][j] accumulates (even-e, odd-e) partials
        unsigned long long sv2[4][4] = {};
        #pragma unroll
        for (int c = 0; c < 16; c++) {
            ulonglong2 q2[4], k2[4];
            #pragma unroll
            for (int i = 0; i < 4; i++)
                q2[i] = *reinterpret_cast<const ulonglong2*>(&Qs[(ty * 4 + i) * 64 + c * 4]);
            const int pc = (c ^ sw) * 4;
            #pragma unroll
            for (int j = 0; j < 4; j++)
                k2[j] = *reinterpret_cast<const ulonglong2*>(&Ks[(tx * 4 + j) * 64 + pc]);
            #pragma unroll
            for (int i = 0; i < 4; i++)
                #pragma unroll
                for (int j = 0; j < 4; j++) {
                    FMA2(sv2[i][j], q2[i].x, k2[j].x);
                    FMA2(sv2[i][j], q2[i].y, k2[j].y);
                }
        }

        // Online softmax per q row (width-16 shfl over the tx lanes)
        #pragma unroll
        for (int i = 0; i < 4; i++) {
            float svr[4];
            #pragma unroll
            for (int j = 0; j < 4; j++) {
                float lo, hi;
                UNPACK2(lo, hi, sv2[i][j]);
                svr[j] = lo + hi;
            }
            float mx = fmaxf(fmaxf(svr[0], svr[1]), fmaxf(svr[2], svr[3]));
            #pragma unroll
            for (int off = 8; off > 0; off >>= 1)
                mx = fmaxf(mx, __shfl_xor_sync(0xffffffffu, mx, off, 16));
            float newm = fmaxf(m_i[i], mx * scale);
            float corr = __expf(m_i[i] - newm);
            m_i[i] = newm;

            float p[4], rsum = 0.f;
            #pragma unroll
            for (int j = 0; j < 4; j++) {
                p[j] = __expf(svr[j] * scale - newm);
                rsum += p[j];
            }
            *reinterpret_cast<float4*>(&Ps[(ty * 4 + i) * 64 + tx * 4]) =
                make_float4(p[0], p[1], p[2], p[3]);
            #pragma unroll
            for (int off = 8; off > 0; off >>= 1)
                rsum += __shfl_xor_sync(0xffffffffu, rsum, off, 16);
            l_i[i] = l_i[i] * corr + rsum;

            unsigned long long corr2;
            PACK2(corr2, corr);
            #pragma unroll
            for (int j = 0; j < 4; j++)
                MUL2(acc[i][j], acc[i][j], corr2);
        }
        __syncthreads();

        // acc += P @ V, packed over key index kk
        #pragma unroll
        for (int c = 0; c < 16; c++) {
            ulonglong2 p2[4], v2[4];
            #pragma unroll
            for (int i = 0; i < 4; i++)
                p2[i] = *reinterpret_cast<const ulonglong2*>(&Ps[(ty * 4 + i) * 64 + c * 4]);
            const int pc = (c ^ sw) * 4;
            #pragma unroll
            for (int j = 0; j < 4; j++)
                v2[j] = *reinterpret_cast<const ulonglong2*>(&Vt[(tx * 4 + j) * 64 + pc]);
            #pragma unroll
            for (int i = 0; i < 4; i++)
                #pragma unroll
                for (int j = 0; j < 4; j++) {
                    FMA2(acc[i][j], p2[i].x, v2[j].x);
                    FMA2(acc[i][j], p2[i].y, v2[j].y);
                }
        }
    }

    // Epilogue: reduce packed halves, normalize, store [H,S,HD]
    #pragma unroll
    for (int i = 0; i < 4; i++) {
        float inv = 1.0f / l_i[i];
        float r[4];
        #pragma unroll
        for (int j = 0; j < 4; j++) {
            float lo, hi;
            UNPACK2(lo, hi, acc[i][j]);
            r[j] = (lo + hi) * inv;
        }
        *reinterpret_cast<float4*>(
            &O[(long)h * SQ * HDIM + (long)(q0 + ty * 4 + i) * HDIM + tx * 4]) =
            make_float4(r[0], r[1], r[2], r[3]);
    }
}

// ---------------------------------------------------------------------------
// Launch: 3 fused launches total
// ---------------------------------------------------------------------------
extern "C" void kernel_launch(void* const* d_in, const int* in_sizes, int n_in,
                              void* d_out, int out_size) {
    const float* GLO = (const float*)d_in[0];
    const float* LOC = (const float*)d_in[1];
    const float* Wq  = (const float*)d_in[2];
    const float* Wk  = (const float*)d_in[3];
    const float* Wv  = (const float*)d_in[4];
    const float* Wo  = (const float*)d_in[5];
    float* out = (float*)d_out;

    float* scratch = nullptr;
    cudaGetSymbolAddress((void**)&scratch, g_scratch);

    cudaFuncSetAttribute(attn_kernel, cudaFuncAttributeMaxDynamicSharedMemorySize, SMEMA);

    proj_kernel<<<dim3(SQ / 128, NH, 6), 256>>>(GLO, LOC, Wq, Wk, Wv, scratch);
    attn_kernel<<<dim3(SQ / 128, NH, 2), 512, SMEMA>>>(scratch, scratch);
    outproj_kernel<<<dim3(SQ / 128, DIM / 64, 2), 256>>>(scratch, Wo, out);
}

// round 11
// speedup vs baseline: 2.0375x; 1.4444x over previous
#include <cuda_runtime.h>
#include <cuda_bf16.h>
#include <cstdint>
#include <math.h>

#define SQ   2048
#define DIM  1024
#define NH   16
#define HDIM 64
#define NELEM (NH * SQ * HDIM)   // floats per [H,S,HD] tensor

// ---------------- scratch (all __device__ globals; no allocs) --------------
__device__ float         g_qkv[6L * NELEM];            // QG,KG,VG,QL,KL,VL fp32
__device__ __nv_bfloat16 g_act[4L * SQ * DIM];         // Ghi,Glo,Lhi,Llo
__device__ __nv_bfloat16 g_w_hi[3L * NH * HDIM * DIM]; // [w][h][n][k]
__device__ __nv_bfloat16 g_w_lo[3L * NH * HDIM * DIM];
__device__ __nv_bfloat16 g_wo_hi[(long)DIM * DIM];     // [n][k]
__device__ __nv_bfloat16 g_wo_lo[(long)DIM * DIM];
__device__ __nv_bfloat16 g_ao[4L * SQ * DIM];          // z0hi,z0lo,z1hi,z1lo

// ---------------- f32x2 helpers (attention kernel) -------------------------
#define FMA2(d, a, b) \
    asm("fma.rn.f32x2 %0, %1, %2, %0;" : "+l"(d) : "l"(a), "l"(b))
#define MUL2(d, a, b) \
    asm("mul.rn.f32x2 %0, %1, %2;" : "=l"(d) : "l"(a), "l"(b))
#define PACK2(d, x) \
    asm("mov.b64 %0, {%1, %1};" : "=l"(d) : "f"(x))
#define UNPACK2(lo, hi, s) \
    asm("mov.b64 {%0, %1}, %2;" : "=f"(lo), "=f"(hi) : "l"(s))

// ---------------- mma.sync / ldmatrix / cp.async helpers (sm_80+ stable) ---
__device__ __forceinline__ uint32_t smem_u32(const void* p) {
    uint32_t a;
    asm("{ .reg .u64 t; cvta.to.shared.u64 t, %1; cvt.u32.u64 %0, t; }"
        : "=r"(a) : "l"(p));
    return a;
}
__device__ __forceinline__ void mma16816(float* d, const uint32_t* a,
                                         const uint32_t* b) {
    asm volatile(
        "mma.sync.aligned.m16n8k16.row.col.f32.bf16.bf16.f32 "
        "{%0,%1,%2,%3}, {%4,%5,%6,%7}, {%8,%9}, {%0,%1,%2,%3};"
        : "+f"(d[0]), "+f"(d[1]), "+f"(d[2]), "+f"(d[3])
        : "r"(a[0]), "r"(a[1]), "r"(a[2]), "r"(a[3]), "r"(b[0]), "r"(b[1]));
}
__device__ __forceinline__ void ldsm_x4(uint32_t* r, uint32_t addr) {
    asm volatile("ldmatrix.sync.aligned.m8n8.x4.shared.b16 {%0,%1,%2,%3}, [%4];"
        : "=r"(r[0]), "=r"(r[1]), "=r"(r[2]), "=r"(r[3]) : "r"(addr));
}
#define CP_ASYNC16(s, g) \
    asm volatile("cp.async.cg.shared.global [%0], [%1], 16;" :: "r"(s), "l"(g))
#define CP_COMMIT() asm volatile("cp.async.commit_group;" ::: "memory")
#define CP_WAIT(n)  asm volatile("cp.async.wait_group %0;" :: "n"(n) : "memory")

// ---------------- bf16 hi/lo split helper ----------------------------------
__device__ __forceinline__ void split2(float a, float b,
                                       __nv_bfloat162& h2, __nv_bfloat162& l2) {
    __nv_bfloat16 ha = __float2bfloat16(a), hb = __float2bfloat16(b);
    __nv_bfloat16 la = __float2bfloat16(a - __bfloat162float(ha));
    __nv_bfloat16 lb = __float2bfloat16(b - __bfloat162float(hb));
    h2 = __nv_bfloat162(ha, hb);
    l2 = __nv_bfloat162(la, lb);
}

// ---------------- convert kernels ------------------------------------------
// GLO/LOC -> bf16 hi/lo.  grid (2048, 2), 256 thr. y: 0=GLO, 1=LOC.
__global__ __launch_bounds__(256)
void conv_act_kernel(const float* __restrict__ GLO, const float* __restrict__ LOC) {
    const float* src = blockIdx.y ? LOC : GLO;
    __nv_bfloat16* hi = g_act + (long)(blockIdx.y * 2 + 0) * SQ * DIM;
    __nv_bfloat16* lo = g_act + (long)(blockIdx.y * 2 + 1) * SQ * DIM;
    long i = (long)blockIdx.x * 256 + threadIdx.x;   // float4 index
    float4 v = reinterpret_cast<const float4*>(src)[i];
    __nv_bfloat162 h0, l0, h1, l1;
    split2(v.x, v.y, h0, l0);
    split2(v.z, v.w, h1, l1);
    reinterpret_cast<__nv_bfloat162*>(hi)[i * 2]     = h0;
    reinterpret_cast<__nv_bfloat162*>(hi)[i * 2 + 1] = h1;
    reinterpret_cast<__nv_bfloat162*>(lo)[i * 2]     = l0;
    reinterpret_cast<__nv_bfloat162*>(lo)[i * 2 + 1] = l1;
}

// W[h][k][n(64)] -> g_w[w][h][n][k] hi/lo.  grid (16 ktiles, NH, 3), 256 thr.
__global__ __launch_bounds__(256)
void conv_w_kernel(const float* __restrict__ Wq, const float* __restrict__ Wk,
                   const float* __restrict__ Wv) {
    __shared__ float t[64][65];
    const int w = blockIdx.z, h = blockIdx.y, k0 = blockIdx.x * 64;
    const int tid = threadIdx.x;
    const float* W = ((w == 0) ? Wq : (w == 1) ? Wk : Wv) + (long)h * DIM * HDIM;
    #pragma unroll
    for (int it = 0; it < 4; it++) {
        int task = tid + it * 256;              // 1024: 64k x 16 float4
        int k = task >> 4, n4 = (task & 15) * 4;
        float4 v = *reinterpret_cast<const float4*>(&W[(long)(k0 + k) * HDIM + n4]);
        t[k][n4] = v.x; t[k][n4 + 1] = v.y; t[k][n4 + 2] = v.z; t[k][n4 + 3] = v.w;
    }
    __syncthreads();
    __nv_bfloat16* dh = g_w_hi + (long)(w * NH + h) * HDIM * DIM + k0;
    __nv_bfloat16* dl = g_w_lo + (long)(w * NH + h) * HDIM * DIM + k0;
    #pragma unroll
    for (int it = 0; it < 8; it++) {
        int task = tid + it * 256;              // 2048: 64n x 32 kpairs
        int n = task >> 5, k2 = (task & 31) * 2;
        __nv_bfloat162 h2, l2;
        split2(t[k2][n], t[k2 + 1][n], h2, l2);
        *reinterpret_cast<__nv_bfloat162*>(&dh[(long)n * DIM + k2]) = h2;
        *reinterpret_cast<__nv_bfloat162*>(&dl[(long)n * DIM + k2]) = l2;
    }
}

// Wo[k][n] -> g_wo[n][k] hi/lo.  grid (16 ktiles, 16 ntiles), 256 thr.
__global__ __launch_bounds__(256)
void conv_wo_kernel(const float* __restrict__ Wo) {
    __shared__ float t[64][65];
    const int k0 = blockIdx.x * 64, n0 = blockIdx.y * 64;
    const int tid = threadIdx.x;
    #pragma unroll
    for (int it = 0; it < 4; it++) {
        int task = tid + it * 256;
        int k = task >> 4, n4 = (task & 15) * 4;
        float4 v = *reinterpret_cast<const float4*>(&Wo[(long)(k0 + k) * DIM + n0 + n4]);
        t[k][n4] = v.x; t[k][n4 + 1] = v.y; t[k][n4 + 2] = v.z; t[k][n4 + 3] = v.w;
    }
    __syncthreads();
    #pragma unroll
    for (int it = 0; it < 8; it++) {
        int task = tid + it * 256;
        int n = task >> 5, k2 = (task & 31) * 2;
        __nv_bfloat162 h2, l2;
        split2(t[k2][n], t[k2 + 1][n], h2, l2);
        *reinterpret_cast<__nv_bfloat162*>(&g_wo_hi[(long)(n0 + n) * DIM + k0 + k2]) = h2;
        *reinterpret_cast<__nv_bfloat162*>(&g_wo_lo[(long)(n0 + n) * DIM + k0 + k2]) = l2;
    }
}

// ---------------- mma.sync bf16-split GEMM ---------------------------------
// D[128m x 128n] = A[m][k] * B[n][k]^T over K=1024, 3-term bf16 hi/lo split.
// 512 threads = 16 warps in 4x4 grid, 32x32 per warp, k-chunks of 32,
// cp.async double buffering. smem rows padded to 80B.
// mode 0 (proj):   grid (16, 8 headpairs, 6)  C -> g_qkv [H][S][64] fp32
// mode 1 (outproj):grid (16, 8 nblocks, 2)    C -> out   [z][S][1024] fp32
#define ROWB        80
#define TEN_BYTES   (128 * ROWB)        // 10240 per tensor buffer
#define STAGE_BYTES (4 * TEN_BYTES)     // Ahi,Alo,Bhi,Blo
#define SM_MMA      (2 * STAGE_BYTES)   // 81920 double-buffered

__global__ __launch_bounds__(512)
void mma_gemm_kernel(float* __restrict__ Cout, int mode) {
    extern __shared__ char smc[];
    const uint32_t sb = smem_u32(smc);
    const int tid = threadIdx.x;
    const int wid = tid >> 5, lane = tid & 31;
    const int wr = wid >> 2, wc = wid & 3;       // 4x4 warp grid
    const int m0 = blockIdx.x * 128;

    const __nv_bfloat16 *Ahi, *Alo, *Bhi, *Blo;
    float *C0, *C1;
    int ldc;
    if (mode == 0) {
        const int z = blockIdx.z, hp = blockIdx.y;
        const int act = (z < 3) ? 0 : 1, w = (z < 3) ? z : z - 3;
        Ahi = g_act + (long)(act * 2 + 0) * SQ * DIM;
        Alo = g_act + (long)(act * 2 + 1) * SQ * DIM;
        Bhi = g_w_hi + (long)(w * NH + hp * 2) * HDIM * DIM;
        Blo = g_w_lo + (long)(w * NH + hp * 2) * HDIM * DIM;
        C0 = g_qkv + (long)z * NELEM + (long)(hp * 2) * SQ * HDIM + (long)m0 * HDIM;
        C1 = C0 + (long)SQ * HDIM;
        ldc = HDIM;
    } else {
        const int z = blockIdx.z, n0 = blockIdx.y * 128;
        Ahi = g_ao + (long)(z * 2 + 0) * SQ * DIM;
        Alo = g_ao + (long)(z * 2 + 1) * SQ * DIM;
        Bhi = g_wo_hi + (long)n0 * DIM;
        Blo = g_wo_lo + (long)n0 * DIM;
        C0 = Cout + (long)z * SQ * DIM + (long)m0 * DIM + n0;
        C1 = C0 + 64;
        ldc = DIM;
    }

    const char* src[4] = {
        (const char*)(Ahi + (long)m0 * DIM), (const char*)(Alo + (long)m0 * DIM),
        (const char*)Bhi, (const char*)Blo };

    // cp.async coords: each thread loads one 16B per tensor per stage
    const int lr = tid >> 2;            // row 0..127
    const int lcb = (tid & 3) * 16;     // 16B chunk within 64B k-slab

    // ldmatrix per-lane byte offsets (within one tensor buffer)
    // A x4 -> frags (m0:8,k0:8)(m8:16,k0:8)(m0:8,k8:16)(m8:16,k8:16)
    const int aRow = wr * 32 + (lane & 7) + ((lane >> 3) & 1) * 8;
    const int aK8  = lane >> 4;                       // 0/1 -> +8 k
    const int aByte = aRow * ROWB + aK8 * 16;
    // B x4 -> frags (n0:8,k0:8)(n0:8,k8:16)(n8:16,k0:8)(n8:16,k8:16)
    const int bRow = wc * 32 + (lane & 7) + ((lane >> 4) & 1) * 8;
    const int bK8  = (lane >> 3) & 1;
    const int bByte = bRow * ROWB + bK8 * 16;

    float acc[2][4][4] = {};   // [mtile][ntile][frag]

    // prologue: load chunk 0 into stage 0
    #pragma unroll
    for (int t = 0; t < 4; t++)
        CP_ASYNC16(sb + t * TEN_BYTES + lr * ROWB + lcb,
                   src[t] + (long)lr * 2048 + lcb);
    CP_COMMIT();

    for (int c = 0; c < 32; c++) {
        if (c + 1 < 32) {
            const uint32_t so = sb + ((c + 1) & 1) * STAGE_BYTES;
            const long go = (long)(c + 1) * 64;
            #pragma unroll
            for (int t = 0; t < 4; t++)
                CP_ASYNC16(so + t * TEN_BYTES + lr * ROWB + lcb,
                           src[t] + (long)lr * 2048 + go + lcb);
            CP_COMMIT();
            CP_WAIT(1);
        } else {
            CP_WAIT(0);
        }
        __syncthreads();

        const uint32_t st = sb + (c & 1) * STAGE_BYTES;
        #pragma unroll
        for (int ks = 0; ks < 2; ks++) {
            uint32_t ah[2][4], al[2][4], bh[2][4], bl[2][4];
            #pragma unroll
            for (int mt = 0; mt < 2; mt++) {
                ldsm_x4(ah[mt], st + 0 * TEN_BYTES + aByte + mt * 16 * ROWB + ks * 32);
                ldsm_x4(al[mt], st + 1 * TEN_BYTES + aByte + mt * 16 * ROWB + ks * 32);
            }
            #pragma unroll
            for (int np = 0; np < 2; np++) {
                ldsm_x4(bh[np], st + 2 * TEN_BYTES + bByte + np * 16 * ROWB + ks * 32);
                ldsm_x4(bl[np], st + 3 * TEN_BYTES + bByte + np * 16 * ROWB + ks * 32);
            }
            #pragma unroll
            for (int mt = 0; mt < 2; mt++)
                #pragma unroll
                for (int nt = 0; nt < 4; nt++) {
                    const uint32_t* fh = &bh[nt >> 1][(nt & 1) * 2];
                    const uint32_t* fl = &bl[nt >> 1][(nt & 1) * 2];
                    mma16816(acc[mt][nt], ah[mt], fh);
                    mma16816(acc[mt][nt], ah[mt], fl);
                    mma16816(acc[mt][nt], al[mt], fh);
                }
        }
        __syncthreads();
    }

    // Epilogue: C fragment: (row l/4, col (l%4)*2+{0,1}) and row +8.
    const int rrel = wr * 32 + (lane >> 2);
    #pragma unroll
    for (int mt = 0; mt < 2; mt++)
        #pragma unroll
        for (int nt = 0; nt < 4; nt++) {
            int ncol = wc * 32 + nt * 8 + (lane & 3) * 2;
            float* P = (ncol >= 64) ? C1 : C0;
            int col = ncol & 63;
            *reinterpret_cast<float2*>(&P[(long)(rrel + mt * 16) * ldc + col]) =
                make_float2(acc[mt][nt][0], acc[mt][nt][1]);
            *reinterpret_cast<float2*>(&P[(long)(rrel + mt * 16 + 8) * ldc + col]) =
                make_float2(acc[mt][nt][2], acc[mt][nt][3]);
        }
}

// ---------------- flash attention (f32x2; bf16 hi/lo epilogue) -------------
#define SMEMA ((128 + 64 + 64 + 128) * 64 * 4)   // 98304 bytes

__global__ __launch_bounds__(512)
void attn_kernel() {
    extern __shared__ float sm[];
    float* Qs = sm;                  // 128 x 64
    float* Ks = sm + 128 * 64;       // 64 x 64 (swizzled)
    float* Vt = sm + 192 * 64;       // 64 x 64 (transposed + swizzled)
    float* Ps = sm + 256 * 64;       // 128 x 64

    const int z = blockIdx.z;
    const float* Q = g_qkv + (long)(z ? 3 : 0) * NELEM;
    const float* K = g_qkv + (long)(z ? 1 : 4) * NELEM;
    const float* V = g_qkv + (long)(z ? 2 : 5) * NELEM;
    __nv_bfloat16* AOhi = g_ao + (long)(z * 2 + 0) * SQ * DIM;
    __nv_bfloat16* AOlo = g_ao + (long)(z * 2 + 1) * SQ * DIM;

    const int h  = blockIdx.y;
    const int q0 = blockIdx.x * 128;
    const float* Qh = Q + (long)h * SQ * HDIM;
    const float* Kh = K + (long)h * SQ * HDIM;
    const float* Vh = V + (long)h * SQ * HDIM;

    const int tid = threadIdx.x;
    const int tx = tid & 15;
    const int ty = tid >> 4;
    const int sw = tx & 7;

    #pragma unroll
    for (int it = 0; it < 4; it++) {
        int task = tid + it * 512;
        int r = task >> 4, c4 = (task & 15) * 4;
        *reinterpret_cast<float4*>(&Qs[r * 64 + c4]) =
            *reinterpret_cast<const float4*>(&Qh[(long)(q0 + r) * HDIM + c4]);
    }

    float m_i[4], l_i[4];
    unsigned long long acc[4][4] = {};
    #pragma unroll
    for (int i = 0; i < 4; i++) { m_i[i] = -1e30f; l_i[i] = 0.f; }
    const float scale = 0.125f;

    for (int j0 = 0; j0 < SQ; j0 += 64) {
        __syncthreads();
        #pragma unroll
        for (int it = 0; it < 2; it++) {
            int task = tid + it * 512;
            int r = task >> 4;
            int ci = task & 15;
            int c4 = ci * 4;
            *reinterpret_cast<float4*>(&Ks[r * 64 + ((ci ^ ((r >> 2) & 7)) << 2)]) =
                *reinterpret_cast<const float4*>(&Kh[(long)(j0 + r) * HDIM + c4]);
            float4 v = *reinterpret_cast<const float4*>(&Vh[(long)(j0 + r) * HDIM + c4]);
            int colp = (((r >> 2) ^ (ci & 7)) << 2) + (r & 3);
            Vt[(c4 + 0) * 64 + colp] = v.x;
            Vt[(c4 + 1) * 64 + colp] = v.y;
            Vt[(c4 + 2) * 64 + colp] = v.z;
            Vt[(c4 + 3) * 64 + colp] = v.w;
        }
        __syncthreads();

        unsigned long long sv2[4][4] = {};
        #pragma unroll
        for (int c = 0; c < 16; c++) {
            ulonglong2 q2[4], k2[4];
            #pragma unroll
            for (int i = 0; i < 4; i++)
                q2[i] = *reinterpret_cast<const ulonglong2*>(&Qs[(ty * 4 + i) * 64 + c * 4]);
            const int pc = (c ^ sw) * 4;
            #pragma unroll
            for (int j = 0; j < 4; j++)
                k2[j] = *reinterpret_cast<const ulonglong2*>(&Ks[(tx * 4 + j) * 64 + pc]);
            #pragma unroll
            for (int i = 0; i < 4; i++)
                #pragma unroll
                for (int j = 0; j < 4; j++) {
                    FMA2(sv2[i][j], q2[i].x, k2[j].x);
                    FMA2(sv2[i][j], q2[i].y, k2[j].y);
                }
        }

        #pragma unroll
        for (int i = 0; i < 4; i++) {
            float svr[4];
            #pragma unroll
            for (int j = 0; j < 4; j++) {
                float lo, hi;
                UNPACK2(lo, hi, sv2[i][j]);
                svr[j] = lo + hi;
            }
            float mx = fmaxf(fmaxf(svr[0], svr[1]), fmaxf(svr[2], svr[3]));
            #pragma unroll
            for (int off = 8; off > 0; off >>= 1)
                mx = fmaxf(mx, __shfl_xor_sync(0xffffffffu, mx, off, 16));
            float newm = fmaxf(m_i[i], mx * scale);
            float corr = __expf(m_i[i] - newm);
            m_i[i] = newm;

            float p[4], rsum = 0.f;
            #pragma unroll
            for (int j = 0; j < 4; j++) {
                p[j] = __expf(svr[j] * scale - newm);
                rsum += p[j];
            }
            *reinterpret_cast<float4*>(&Ps[(ty * 4 + i) * 64 + tx * 4]) =
                make_float4(p[0], p[1], p[2], p[3]);
            #pragma unroll
            for (int off = 8; off > 0; off >>= 1)
                rsum += __shfl_xor_sync(0xffffffffu, rsum, off, 16);
            l_i[i] = l_i[i] * corr + rsum;

            unsigned long long corr2;
            PACK2(corr2, corr);
            #pragma unroll
            for (int j = 0; j < 4; j++)
                MUL2(acc[i][j], acc[i][j], corr2);
        }
        __syncthreads();

        #pragma unroll
        for (int c = 0; c < 16; c++) {
            ulonglong2 p2[4], v2[4];
            #pragma unroll
            for (int i = 0; i < 4; i++)
                p2[i] = *reinterpret_cast<const ulonglong2*>(&Ps[(ty * 4 + i) * 64 + c * 4]);
            const int pc = (c ^ sw) * 4;
            #pragma unroll
            for (int j = 0; j < 4; j++)
                v2[j] = *reinterpret_cast<const ulonglong2*>(&Vt[(tx * 4 + j) * 64 + pc]);
            #pragma unroll
            for (int i = 0; i < 4; i++)
                #pragma unroll
                for (int j = 0; j < 4; j++) {
                    FMA2(acc[i][j], p2[i].x, v2[j].x);
                    FMA2(acc[i][j], p2[i].y, v2[j].y);
                }
        }
    }

    // Epilogue: normalize; write bf16 hi/lo at the FLAT VIEW of [H][S][HD]
    // (faithful to the reference's raw reshape — no head transpose).
    #pragma unroll
    for (int i = 0; i < 4; i++) {
        float inv = 1.0f / l_i[i];
        float r[4];
        #pragma unroll
        for (int j = 0; j < 4; j++) {
            float lo, hi;
            UNPACK2(lo, hi, acc[i][j]);
            r[j] = (lo + hi) * inv;
        }
        long base = (long)h * SQ * HDIM + (long)(q0 + ty * 4 + i) * HDIM + tx * 4;
        __nv_bfloat162 h0, l0, h1, l1;
        split2(r[0], r[1], h0, l0);
        split2(r[2], r[3], h1, l1);
        *reinterpret_cast<__nv_bfloat162*>(&AOhi[base])     = h0;
        *reinterpret_cast<__nv_bfloat162*>(&AOhi[base + 2]) = h1;
        *reinterpret_cast<__nv_bfloat162*>(&AOlo[base])     = l0;
        *reinterpret_cast<__nv_bfloat162*>(&AOlo[base + 2]) = l1;
    }
}

// ---------------- launch ----------------------------------------------------
extern "C" void kernel_launch(void* const* d_in, const int* in_sizes, int n_in,
                              void* d_out, int out_size) {
    const float* GLO = (const float*)d_in[0];
    const float* LOC = (const float*)d_in[1];
    const float* Wq  = (const float*)d_in[2];
    const float* Wk  = (const float*)d_in[3];
    const float* Wv  = (const float*)d_in[4];
    const float* Wo  = (const float*)d_in[5];
    float* out = (float*)d_out;

    cudaFuncSetAttribute(mma_gemm_kernel, cudaFuncAttributeMaxDynamicSharedMemorySize, SM_MMA);
    cudaFuncSetAttribute(attn_kernel, cudaFuncAttributeMaxDynamicSharedMemorySize, SMEMA);

    conv_act_kernel<<<dim3(2048, 2), 256>>>(GLO, LOC);
    conv_w_kernel<<<dim3(16, NH, 3), 256>>>(Wq, Wk, Wv);
    conv_wo_kernel<<<dim3(16, 16), 256>>>(Wo);

    mma_gemm_kernel<<<dim3(16, 8, 6), 512, SM_MMA>>>(out, 0);   // projections
    attn_kernel<<<dim3(16, NH, 2), 512, SMEMA>>>();
    mma_gemm_kernel<<<dim3(16, 8, 2), 512, SM_MMA>>>(out, 1);   // out-proj
}

// round 12
// speedup vs baseline: 3.8467x; 1.8879x over previous
#include <cuda_runtime.h>
#include <cuda_bf16.h>
#include <cstdint>
#include <math.h>

#define SQ   2048
#define DIM  1024
#define NH   16
#define HDIM 64
#define NELEM (NH * SQ * HDIM)   // elems per [H,S,HD] tensor

// ---------------- scratch (all __device__ globals; no allocs) --------------
__device__ __nv_bfloat16 g_qkvh[6L * NELEM];           // Q,K,V hi  [z][h][s][64]
__device__ __nv_bfloat16 g_qkvl[6L * NELEM];           // Q,K,V lo
__device__ __nv_bfloat16 g_act[4L * SQ * DIM];         // Ghi,Glo,Lhi,Llo
__device__ __nv_bfloat16 g_w_hi[3L * NH * HDIM * DIM]; // [w][h][n][k]
__device__ __nv_bfloat16 g_w_lo[3L * NH * HDIM * DIM];
__device__ __nv_bfloat16 g_wo_hi[(long)DIM * DIM];     // [n][k]
__device__ __nv_bfloat16 g_wo_lo[(long)DIM * DIM];
__device__ __nv_bfloat16 g_ao[4L * SQ * DIM];          // z0hi,z0lo,z1hi,z1lo

// ---------------- mma.sync / ldmatrix / cp.async helpers -------------------
__device__ __forceinline__ uint32_t smem_u32(const void* p) {
    uint32_t a;
    asm("{ .reg .u64 t; cvta.to.shared.u64 t, %1; cvt.u32.u64 %0, t; }"
        : "=r"(a) : "l"(p));
    return a;
}
__device__ __forceinline__ void mma16816(float* d, const uint32_t* a,
                                         const uint32_t* b) {
    asm volatile(
        "mma.sync.aligned.m16n8k16.row.col.f32.bf16.bf16.f32 "
        "{%0,%1,%2,%3}, {%4,%5,%6,%7}, {%8,%9}, {%0,%1,%2,%3};"
        : "+f"(d[0]), "+f"(d[1]), "+f"(d[2]), "+f"(d[3])
        : "r"(a[0]), "r"(a[1]), "r"(a[2]), "r"(a[3]), "r"(b[0]), "r"(b[1]));
}
__device__ __forceinline__ void ldsm_x4(uint32_t* r, uint32_t addr) {
    asm volatile("ldmatrix.sync.aligned.m8n8.x4.shared.b16 {%0,%1,%2,%3}, [%4];"
        : "=r"(r[0]), "=r"(r[1]), "=r"(r[2]), "=r"(r[3]) : "r"(addr));
}
__device__ __forceinline__ void ldsm_x4_t(uint32_t* r, uint32_t addr) {
    asm volatile("ldmatrix.sync.aligned.m8n8.x4.trans.shared.b16 {%0,%1,%2,%3}, [%4];"
        : "=r"(r[0]), "=r"(r[1]), "=r"(r[2]), "=r"(r[3]) : "r"(addr));
}
#define CP_ASYNC16(s, g) \
    asm volatile("cp.async.cg.shared.global [%0], [%1], 16;" :: "r"(s), "l"(g))
#define CP_COMMIT() asm volatile("cp.async.commit_group;" ::: "memory")
#define CP_WAIT(n)  asm volatile("cp.async.wait_group %0;" :: "n"(n) : "memory")
#define SWZ(off) ((off) ^ (((off) >> 3) & 0x70))

// ---------------- bf16 hi/lo split helper ----------------------------------
__device__ __forceinline__ void split2(float a, float b,
                                       __nv_bfloat162& h2, __nv_bfloat162& l2) {
    __nv_bfloat16 ha = __float2bfloat16(a), hb = __float2bfloat16(b);
    __nv_bfloat16 la = __float2bfloat16(a - __bfloat162float(ha));
    __nv_bfloat16 lb = __float2bfloat16(b - __bfloat162float(hb));
    h2 = __nv_bfloat162(ha, hb);
    l2 = __nv_bfloat162(la, lb);
}
__device__ __forceinline__ uint32_t b2u(__nv_bfloat162 v) {
    return *reinterpret_cast<uint32_t*>(&v);
}

// ---------------- convert kernels (unchanged) ------------------------------
__global__ __launch_bounds__(256)
void conv_act_kernel(const float* __restrict__ GLO, const float* __restrict__ LOC) {
    const float* src = blockIdx.y ? LOC : GLO;
    __nv_bfloat16* hi = g_act + (long)(blockIdx.y * 2 + 0) * SQ * DIM;
    __nv_bfloat16* lo = g_act + (long)(blockIdx.y * 2 + 1) * SQ * DIM;
    long i = (long)blockIdx.x * 256 + threadIdx.x;
    float4 v = reinterpret_cast<const float4*>(src)[i];
    __nv_bfloat162 h0, l0, h1, l1;
    split2(v.x, v.y, h0, l0);
    split2(v.z, v.w, h1, l1);
    reinterpret_cast<__nv_bfloat162*>(hi)[i * 2]     = h0;
    reinterpret_cast<__nv_bfloat162*>(hi)[i * 2 + 1] = h1;
    reinterpret_cast<__nv_bfloat162*>(lo)[i * 2]     = l0;
    reinterpret_cast<__nv_bfloat162*>(lo)[i * 2 + 1] = l1;
}

__global__ __launch_bounds__(256)
void conv_w_kernel(const float* __restrict__ Wq, const float* __restrict__ Wk,
                   const float* __restrict__ Wv) {
    __shared__ float t[64][65];
    const int w = blockIdx.z, h = blockIdx.y, k0 = blockIdx.x * 64;
    const int tid = threadIdx.x;
    const float* W = ((w == 0) ? Wq : (w == 1) ? Wk : Wv) + (long)h * DIM * HDIM;
    #pragma unroll
    for (int it = 0; it < 4; it++) {
        int task = tid + it * 256;
        int k = task >> 4, n4 = (task & 15) * 4;
        float4 v = *reinterpret_cast<const float4*>(&W[(long)(k0 + k) * HDIM + n4]);
        t[k][n4] = v.x; t[k][n4 + 1] = v.y; t[k][n4 + 2] = v.z; t[k][n4 + 3] = v.w;
    }
    __syncthreads();
    __nv_bfloat16* dh = g_w_hi + (long)(w * NH + h) * HDIM * DIM + k0;
    __nv_bfloat16* dl = g_w_lo + (long)(w * NH + h) * HDIM * DIM + k0;
    #pragma unroll
    for (int it = 0; it < 8; it++) {
        int task = tid + it * 256;
        int n = task >> 5, k2 = (task & 31) * 2;
        __nv_bfloat162 h2, l2;
        split2(t[k2][n], t[k2 + 1][n], h2, l2);
        *reinterpret_cast<__nv_bfloat162*>(&dh[(long)n * DIM + k2]) = h2;
        *reinterpret_cast<__nv_bfloat162*>(&dl[(long)n * DIM + k2]) = l2;
    }
}

__global__ __launch_bounds__(256)
void conv_wo_kernel(const float* __restrict__ Wo) {
    __shared__ float t[64][65];
    const int k0 = blockIdx.x * 64, n0 = blockIdx.y * 64;
    const int tid = threadIdx.x;
    #pragma unroll
    for (int it = 0; it < 4; it++) {
        int task = tid + it * 256;
        int k = task >> 4, n4 = (task & 15) * 4;
        float4 v = *reinterpret_cast<const float4*>(&Wo[(long)(k0 + k) * DIM + n0 + n4]);
        t[k][n4] = v.x; t[k][n4 + 1] = v.y; t[k][n4 + 2] = v.z; t[k][n4 + 3] = v.w;
    }
    __syncthreads();
    #pragma unroll
    for (int it = 0; it < 8; it++) {
        int task = tid + it * 256;
        int n = task >> 5, k2 = (task & 31) * 2;
        __nv_bfloat162 h2, l2;
        split2(t[k2][n], t[k2 + 1][n], h2, l2);
        *reinterpret_cast<__nv_bfloat162*>(&g_wo_hi[(long)(n0 + n) * DIM + k0 + k2]) = h2;
        *reinterpret_cast<__nv_bfloat162*>(&g_wo_lo[(long)(n0 + n) * DIM + k0 + k2]) = l2;
    }
}

// ---------------- mma.sync bf16-split GEMM ---------------------------------
// mode 0 (proj):   C -> g_qkvh/g_qkvl bf16 [z][h][s][64]
// mode 1 (outproj):C -> out fp32 [z][S][1024]
#define ROWB        80
#define TEN_BYTES   (128 * ROWB)
#define STAGE_BYTES (4 * TEN_BYTES)
#define SM_MMA      (2 * STAGE_BYTES)   // 81920

__global__ __launch_bounds__(512)
void mma_gemm_kernel(float* __restrict__ Cout, int mode) {
    extern __shared__ char smc[];
    const uint32_t sb = smem_u32(smc);
    const int tid = threadIdx.x;
    const int wid = tid >> 5, lane = tid & 31;
    const int wr = wid >> 2, wc = wid & 3;
    const int m0 = blockIdx.x * 128;

    const __nv_bfloat16 *Ahi, *Alo, *Bhi, *Blo;
    float *C0f = nullptr, *C1f = nullptr;
    __nv_bfloat16 *C0h = nullptr, *C1h = nullptr, *C0l = nullptr, *C1l = nullptr;
    if (mode == 0) {
        const int z = blockIdx.z, hp = blockIdx.y;
        const int act = (z < 3) ? 0 : 1, w = (z < 3) ? z : z - 3;
        Ahi = g_act + (long)(act * 2 + 0) * SQ * DIM;
        Alo = g_act + (long)(act * 2 + 1) * SQ * DIM;
        Bhi = g_w_hi + (long)(w * NH + hp * 2) * HDIM * DIM;
        Blo = g_w_lo + (long)(w * NH + hp * 2) * HDIM * DIM;
        long coff = (long)z * NELEM + (long)(hp * 2) * SQ * HDIM + (long)m0 * HDIM;
        C0h = g_qkvh + coff; C1h = C0h + (long)SQ * HDIM;
        C0l = g_qkvl + coff; C1l = C0l + (long)SQ * HDIM;
    } else {
        const int z = blockIdx.z, n0 = blockIdx.y * 128;
        Ahi = g_ao + (long)(z * 2 + 0) * SQ * DIM;
        Alo = g_ao + (long)(z * 2 + 1) * SQ * DIM;
        Bhi = g_wo_hi + (long)n0 * DIM;
        Blo = g_wo_lo + (long)n0 * DIM;
        C0f = Cout + (long)z * SQ * DIM + (long)m0 * DIM + n0;
        C1f = C0f + 64;
    }

    const char* src[4] = {
        (const char*)(Ahi + (long)m0 * DIM), (const char*)(Alo + (long)m0 * DIM),
        (const char*)Bhi, (const char*)Blo };

    const int lr = tid >> 2;
    const int lcb = (tid & 3) * 16;

    const int aRow = wr * 32 + (lane & 7) + ((lane >> 3) & 1) * 8;
    const int aByte = aRow * ROWB + (lane >> 4) * 16;
    const int bRow = wc * 32 + (lane & 7) + ((lane >> 4) & 1) * 8;
    const int bByte = bRow * ROWB + ((lane >> 3) & 1) * 16;

    float acc[2][4][4] = {};

    #pragma unroll
    for (int t = 0; t < 4; t++)
        CP_ASYNC16(sb + t * TEN_BYTES + lr * ROWB + lcb,
                   src[t] + (long)lr * 2048 + lcb);
    CP_COMMIT();

    for (int c = 0; c < 32; c++) {
        if (c + 1 < 32) {
            const uint32_t so = sb + ((c + 1) & 1) * STAGE_BYTES;
            const long go = (long)(c + 1) * 64;
            #pragma unroll
            for (int t = 0; t < 4; t++)
                CP_ASYNC16(so + t * TEN_BYTES + lr * ROWB + lcb,
                           src[t] + (long)lr * 2048 + go + lcb);
            CP_COMMIT();
            CP_WAIT(1);
        } else {
            CP_WAIT(0);
        }
        __syncthreads();

        const uint32_t st = sb + (c & 1) * STAGE_BYTES;
        #pragma unroll
        for (int ks = 0; ks < 2; ks++) {
            uint32_t ah[2][4], al[2][4], bh[2][4], bl[2][4];
            #pragma unroll
            for (int mt = 0; mt < 2; mt++) {
                ldsm_x4(ah[mt], st + 0 * TEN_BYTES + aByte + mt * 16 * ROWB + ks * 32);
                ldsm_x4(al[mt], st + 1 * TEN_BYTES + aByte + mt * 16 * ROWB + ks * 32);
            }
            #pragma unroll
            for (int np = 0; np < 2; np++) {
                ldsm_x4(bh[np], st + 2 * TEN_BYTES + bByte + np * 16 * ROWB + ks * 32);
                ldsm_x4(bl[np], st + 3 * TEN_BYTES + bByte + np * 16 * ROWB + ks * 32);
            }
            #pragma unroll
            for (int mt = 0; mt < 2; mt++)
                #pragma unroll
                for (int nt = 0; nt < 4; nt++) {
                    const uint32_t* fh = &bh[nt >> 1][(nt & 1) * 2];
                    const uint32_t* fl = &bl[nt >> 1][(nt & 1) * 2];
                    mma16816(acc[mt][nt], ah[mt], fh);
                    mma16816(acc[mt][nt], ah[mt], fl);
                    mma16816(acc[mt][nt], al[mt], fh);
                }
        }
        __syncthreads();
    }

    const int rrel = wr * 32 + (lane >> 2);
    #pragma unroll
    for (int mt = 0; mt < 2; mt++)
        #pragma unroll
        for (int nt = 0; nt < 4; nt++) {
            int ncol = wc * 32 + nt * 8 + (lane & 3) * 2;
            int col = ncol & 63;
            long r0 = rrel + mt * 16, r1 = r0 + 8;
            if (mode == 0) {
                __nv_bfloat16* Ph = (ncol >= 64) ? C1h : C0h;
                __nv_bfloat16* Pl = (ncol >= 64) ? C1l : C0l;
                __nv_bfloat162 h2, l2;
                split2(acc[mt][nt][0], acc[mt][nt][1], h2, l2);
                *reinterpret_cast<uint32_t*>(&Ph[r0 * 64 + col]) = b2u(h2);
                *reinterpret_cast<uint32_t*>(&Pl[r0 * 64 + col]) = b2u(l2);
                split2(acc[mt][nt][2], acc[mt][nt][3], h2, l2);
                *reinterpret_cast<uint32_t*>(&Ph[r1 * 64 + col]) = b2u(h2);
                *reinterpret_cast<uint32_t*>(&Pl[r1 * 64 + col]) = b2u(l2);
            } else {
                float* P = (ncol >= 64) ? C1f : C0f;
                *reinterpret_cast<float2*>(&P[r0 * DIM + col]) =
                    make_float2(acc[mt][nt][0], acc[mt][nt][1]);
                *reinterpret_cast<float2*>(&P[r1 * DIM + col]) =
                    make_float2(acc[mt][nt][2], acc[mt][nt][3]);
            }
        }
}

// ---------------- mma.sync flash attention ---------------------------------
// 256 thr = 8 warps x 16 q-rows. K-tiles of 64 keys, double-buffered cp.async.
// smem: Qhi/Qlo 128x128B swz; per stage: Khi,Klo,Vhi,Vlo 64x128B swz.
#define AT_Q   0
#define AT_KV  32768
#define AT_STG 32768
#define SMEMA  (32768 + 2 * 32768)   // 98304

__global__ __launch_bounds__(256)
void attn_kernel() {
    extern __shared__ char sma[];
    const uint32_t sb = smem_u32(sma);
    const int tid = threadIdx.x, lane = tid & 31, warp = tid >> 5;
    const int z = blockIdx.z, h = blockIdx.y, q0 = blockIdx.x * 128;

    const long hoff = (long)h * SQ * HDIM;
    const __nv_bfloat16* Qh_ = g_qkvh + (long)(z ? 3 : 0) * NELEM + hoff;
    const __nv_bfloat16* Ql_ = g_qkvl + (long)(z ? 3 : 0) * NELEM + hoff;
    const __nv_bfloat16* Kh_ = g_qkvh + (long)(z ? 1 : 4) * NELEM + hoff;
    const __nv_bfloat16* Kl_ = g_qkvl + (long)(z ? 1 : 4) * NELEM + hoff;
    const __nv_bfloat16* Vh_ = g_qkvh + (long)(z ? 2 : 5) * NELEM + hoff;
    const __nv_bfloat16* Vl_ = g_qkvl + (long)(z ? 2 : 5) * NELEM + hoff;
    __nv_bfloat16* AOhi = g_ao + (long)(z * 2 + 0) * SQ * DIM;
    __nv_bfloat16* AOlo = g_ao + (long)(z * 2 + 1) * SQ * DIM;

    // prologue: Q (hi+lo) + KV stage 0
    #pragma unroll
    for (int it = 0; it < 4; it++) {
        int task = tid + it * 256;        // 1024: 128 rows x 8 chunks
        int r = task >> 3, c = task & 7;
        uint32_t d = SWZ(r * 128 + c * 16);
        CP_ASYNC16(sb + AT_Q + d,         (const char*)(Qh_ + (long)(q0 + r) * 64) + c * 16);
        CP_ASYNC16(sb + AT_Q + 16384 + d, (const char*)(Ql_ + (long)(q0 + r) * 64) + c * 16);
    }
    #pragma unroll
    for (int it = 0; it < 2; it++) {
        int task = tid + it * 256;        // 512: 64 rows x 8 chunks
        int r = task >> 3, c = task & 7;
        uint32_t d = SWZ(r * 128 + c * 16);
        const long g = (long)r * 64;
        CP_ASYNC16(sb + AT_KV + 0     + d, (const char*)(Kh_ + g) + c * 16);
        CP_ASYNC16(sb + AT_KV + 8192  + d, (const char*)(Kl_ + g) + c * 16);
        CP_ASYNC16(sb + AT_KV + 16384 + d, (const char*)(Vh_ + g) + c * 16);
        CP_ASYNC16(sb + AT_KV + 24576 + d, (const char*)(Vl_ + g) + c * 16);
    }
    CP_COMMIT();

    uint32_t qh[4][4], ql[4][4];
    float acc[8][4] = {};
    float m0 = -1e30f, m1 = -1e30f, l0 = 0.f, l1 = 0.f;
    const float scale = 0.125f;

    // ldmatrix lane addressing (byte offsets inside one 64x128B tensor)
    const int aRow = warp * 16 + (lane & 7) + ((lane >> 3) & 1) * 8;  // Q rows
    const int aC   = lane >> 4;
    const int kRowBase = (lane & 7) + ((lane >> 4) & 1) * 8;          // K n-rows
    const int kC   = (lane >> 3) & 1;
    const int vRowBase = (lane & 7) + ((lane >> 3) & 1) * 8;          // V k-rows
    const int vC   = lane >> 4;

    for (int j = 0; j < 32; j++) {
        __syncthreads();   // stage (j+1)&1 free of previous readers
        if (j + 1 < 32) {
            const uint32_t so = sb + AT_KV + ((j + 1) & 1) * AT_STG;
            const long j1 = (long)(j + 1) * 64;
            #pragma unroll
            for (int it = 0; it < 2; it++) {
                int task = tid + it * 256;
                int r = task >> 3, c = task & 7;
                uint32_t d = SWZ(r * 128 + c * 16);
                const long g = (j1 + r) * 64;
                CP_ASYNC16(so + 0     + d, (const char*)(Kh_ + g) + c * 16);
                CP_ASYNC16(so + 8192  + d, (const char*)(Kl_ + g) + c * 16);
                CP_ASYNC16(so + 16384 + d, (const char*)(Vh_ + g) + c * 16);
                CP_ASYNC16(so + 24576 + d, (const char*)(Vl_ + g) + c * 16);
            }
            CP_COMMIT();
            CP_WAIT(1);
        } else {
            CP_WAIT(0);
        }
        __syncthreads();

        if (j == 0) {   // Q fragments, loaded once
            #pragma unroll
            for (int kc = 0; kc < 4; kc++) {
                uint32_t ad = sb + AT_Q + SWZ(aRow * 128 + (kc * 2 + aC) * 16);
                ldsm_x4(qh[kc], ad);
                ldsm_x4(ql[kc], ad + 16384);
            }
        }

        const uint32_t kv = sb + AT_KV + (j & 1) * AT_STG;

        // ---- S = Q K^T (3-term split), raw fp32 scores -------------------
        float s[8][4] = {};
        #pragma unroll
        for (int nb = 0; nb < 4; nb++) {
            #pragma unroll
            for (int kc = 0; kc < 4; kc++) {
                uint32_t kh[4], kl[4];
                uint32_t ad = kv + SWZ((nb * 16 + kRowBase) * 128 + (kc * 2 + kC) * 16);
                ldsm_x4(kh, ad);
                ldsm_x4(kl, ad + 8192);
                mma16816(s[nb * 2],     qh[kc], kh);
                mma16816(s[nb * 2],     qh[kc], kl);
                mma16816(s[nb * 2],     ql[kc], kh);
                mma16816(s[nb * 2 + 1], qh[kc], kh + 2);
                mma16816(s[nb * 2 + 1], qh[kc], kl + 2);
                mma16816(s[nb * 2 + 1], ql[kc], kh + 2);
            }
        }

        // ---- online softmax (rows r0=lane/4, r1=r0+8 within warp tile) ---
        float mx0 = -1e30f, mx1 = -1e30f;
        #pragma unroll
        for (int nt = 0; nt < 8; nt++) {
            mx0 = fmaxf(mx0, fmaxf(s[nt][0], s[nt][1]));
            mx1 = fmaxf(mx1, fmaxf(s[nt][2], s[nt][3]));
        }
        #pragma unroll
        for (int off = 1; off <= 2; off <<= 1) {
            mx0 = fmaxf(mx0, __shfl_xor_sync(0xffffffffu, mx0, off));
            mx1 = fmaxf(mx1, __shfl_xor_sync(0xffffffffu, mx1, off));
        }
        float nm0 = fmaxf(m0, mx0 * scale), nm1 = fmaxf(m1, mx1 * scale);
        float cr0 = __expf(m0 - nm0), cr1 = __expf(m1 - nm1);
        m0 = nm0; m1 = nm1;

        uint32_t pah0[8], pal0[8], pah1[8], pal1[8];
        float rs0 = 0.f, rs1 = 0.f;
        #pragma unroll
        for (int nt = 0; nt < 8; nt++) {
            float p0 = __expf(s[nt][0] * scale - m0);
            float p1 = __expf(s[nt][1] * scale - m0);
            float p2 = __expf(s[nt][2] * scale - m1);
            float p3 = __expf(s[nt][3] * scale - m1);
            rs0 += p0 + p1; rs1 += p2 + p3;
            __nv_bfloat162 h2, l2;
            split2(p0, p1, h2, l2);
            pah0[nt] = b2u(h2); pal0[nt] = b2u(l2);
            split2(p2, p3, h2, l2);
            pah1[nt] = b2u(h2); pal1[nt] = b2u(l2);
        }
        #pragma unroll
        for (int off = 1; off <= 2; off <<= 1) {
            rs0 += __shfl_xor_sync(0xffffffffu, rs0, off);
            rs1 += __shfl_xor_sync(0xffffffffu, rs1, off);
        }
        l0 = l0 * cr0 + rs0;
        l1 = l1 * cr1 + rs1;
        #pragma unroll
        for (int nt = 0; nt < 8; nt++) {
            acc[nt][0] *= cr0; acc[nt][1] *= cr0;
            acc[nt][2] *= cr1; acc[nt][3] *= cr1;
        }

        // ---- acc += P V (3-term split); V via ldmatrix.trans -------------
        #pragma unroll
        for (int nb = 0; nb < 4; nb++) {
            #pragma unroll
            for (int kc = 0; kc < 4; kc++) {
                uint32_t vh[4], vl[4];
                uint32_t ad = kv + 16384 +
                    SWZ((kc * 16 + vRowBase) * 128 + (nb * 2 + vC) * 16);
                ldsm_x4_t(vh, ad);
                ldsm_x4_t(vl, ad + 8192);
                uint32_t ah[4] = { pah0[2*kc], pah1[2*kc], pah0[2*kc+1], pah1[2*kc+1] };
                uint32_t al[4] = { pal0[2*kc], pal1[2*kc], pal0[2*kc+1], pal1[2*kc+1] };
                mma16816(acc[nb * 2],     ah, vh);
                mma16816(acc[nb * 2],     ah, vl);
                mma16816(acc[nb * 2],     al, vh);
                mma16816(acc[nb * 2 + 1], ah, vh + 2);
                mma16816(acc[nb * 2 + 1], ah, vl + 2);
                mma16816(acc[nb * 2 + 1], al, vh + 2);
            }
        }
    }

    // ---- epilogue: normalize, split, store at flat [h][s][64] view --------
    const float inv0 = 1.0f / l0, inv1 = 1.0f / l1;
    const long r0 = q0 + warp * 16 + (lane >> 2);
    #pragma unroll
    for (int nt = 0; nt < 8; nt++) {
        int e = nt * 8 + (lane & 3) * 2;
        long i0 = (long)h * SQ * HDIM + r0 * HDIM + e;
        long i1 = i0 + 8L * HDIM;
        __nv_bfloat162 h2, l2;
        split2(acc[nt][0] * inv0, acc[nt][1] * inv0, h2, l2);
        *reinterpret_cast<uint32_t*>(&AOhi[i0]) = b2u(h2);
        *reinterpret_cast<uint32_t*>(&AOlo[i0]) = b2u(l2);
        split2(acc[nt][2] * inv1, acc[nt][3] * inv1, h2, l2);
        *reinterpret_cast<uint32_t*>(&AOhi[i1]) = b2u(h2);
        *reinterpret_cast<uint32_t*>(&AOlo[i1]) = b2u(l2);
    }
}

// ---------------- launch ----------------------------------------------------
extern "C" void kernel_launch(void* const* d_in, const int* in_sizes, int n_in,
                              void* d_out, int out_size) {
    const float* GLO = (const float*)d_in[0];
    const float* LOC = (const float*)d_in[1];
    const float* Wq  = (const float*)d_in[2];
    const float* Wk  = (const float*)d_in[3];
    const float* Wv  = (const float*)d_in[4];
    const float* Wo  = (const float*)d_in[5];
    float* out = (float*)d_out;

    cudaFuncSetAttribute(mma_gemm_kernel, cudaFuncAttributeMaxDynamicSharedMemorySize, SM_MMA);
    cudaFuncSetAttribute(attn_kernel, cudaFuncAttributeMaxDynamicSharedMemorySize, SMEMA);

    conv_act_kernel<<<dim3(2048, 2), 256>>>(GLO, LOC);
    conv_w_kernel<<<dim3(16, NH, 3), 256>>>(Wq, Wk, Wv);
    conv_wo_kernel<<<dim3(16, 16), 256>>>(Wo);

    mma_gemm_kernel<<<dim3(16, 8, 6), 512, SM_MMA>>>(out, 0);   // projections
    attn_kernel<<<dim3(16, NH, 2), 256, SMEMA>>>();
    mma_gemm_kernel<<<dim3(16, 8, 2), 512, SM_MMA>>>(out, 1);   // out-proj
}

// round 13
// speedup vs baseline: 4.1086x; 1.0681x over previous
#include <cuda_runtime.h>
#include <cuda_bf16.h>
#include <cstdint>
#include <math.h>

#define SQ   2048
#define DIM  1024
#define NH   16
#define HDIM 64
#define NELEM (NH * SQ * HDIM)   // elems per [H,S,HD] tensor

// ---------------- scratch (all __device__ globals; no allocs) --------------
__device__ __nv_bfloat16 g_qkvh[6L * NELEM];           // Q,K,V hi  [z][h][s][64]
__device__ __nv_bfloat16 g_qkvl[6L * NELEM];           // Q,K,V lo
__device__ __nv_bfloat16 g_act[4L * SQ * DIM];         // Ghi,Glo,Lhi,Llo
__device__ __nv_bfloat16 g_w_hi[3L * NH * HDIM * DIM]; // [w][h][n][k]
__device__ __nv_bfloat16 g_w_lo[3L * NH * HDIM * DIM];
__device__ __nv_bfloat16 g_wo_hi[(long)DIM * DIM];     // [n][k]
__device__ __nv_bfloat16 g_wo_lo[(long)DIM * DIM];
__device__ __nv_bfloat16 g_ao[4L * SQ * DIM];          // z0hi,z0lo,z1hi,z1lo

// ---------------- mma.sync / ldmatrix / cp.async helpers -------------------
__device__ __forceinline__ uint32_t smem_u32(const void* p) {
    uint32_t a;
    asm("{ .reg .u64 t; cvta.to.shared.u64 t, %1; cvt.u32.u64 %0, t; }"
        : "=r"(a) : "l"(p));
    return a;
}
__device__ __forceinline__ void mma16816(float* d, const uint32_t* a,
                                         const uint32_t* b) {
    asm volatile(
        "mma.sync.aligned.m16n8k16.row.col.f32.bf16.bf16.f32 "
        "{%0,%1,%2,%3}, {%4,%5,%6,%7}, {%8,%9}, {%0,%1,%2,%3};"
        : "+f"(d[0]), "+f"(d[1]), "+f"(d[2]), "+f"(d[3])
        : "r"(a[0]), "r"(a[1]), "r"(a[2]), "r"(a[3]), "r"(b[0]), "r"(b[1]));
}
__device__ __forceinline__ void ldsm_x4(uint32_t* r, uint32_t addr) {
    asm volatile("ldmatrix.sync.aligned.m8n8.x4.shared.b16 {%0,%1,%2,%3}, [%4];"
        : "=r"(r[0]), "=r"(r[1]), "=r"(r[2]), "=r"(r[3]) : "r"(addr));
}
__device__ __forceinline__ void ldsm_x4_t(uint32_t* r, uint32_t addr) {
    asm volatile("ldmatrix.sync.aligned.m8n8.x4.trans.shared.b16 {%0,%1,%2,%3}, [%4];"
        : "=r"(r[0]), "=r"(r[1]), "=r"(r[2]), "=r"(r[3]) : "r"(addr));
}
#define CP_ASYNC16(s, g) \
    asm volatile("cp.async.cg.shared.global [%0], [%1], 16;" :: "r"(s), "l"(g))
#define CP_COMMIT() asm volatile("cp.async.commit_group;" ::: "memory")
#define CP_WAIT(n)  asm volatile("cp.async.wait_group %0;" :: "n"(n) : "memory")
#define SWZ(off) ((off) ^ (((off) >> 3) & 0x70))

// ---------------- bf16 hi/lo split helper ----------------------------------
__device__ __forceinline__ void split2(float a, float b,
                                       __nv_bfloat162& h2, __nv_bfloat162& l2) {
    __nv_bfloat16 ha = __float2bfloat16(a), hb = __float2bfloat16(b);
    __nv_bfloat16 la = __float2bfloat16(a - __bfloat162float(ha));
    __nv_bfloat16 lb = __float2bfloat16(b - __bfloat162float(hb));
    h2 = __nv_bfloat162(ha, hb);
    l2 = __nv_bfloat162(la, lb);
}
__device__ __forceinline__ uint32_t b2u(__nv_bfloat162 v) {
    return *reinterpret_cast<uint32_t*>(&v);
}

// ---------------- convert kernels ------------------------------------------
__global__ __launch_bounds__(256)
void conv_act_kernel(const float* __restrict__ GLO, const float* __restrict__ LOC) {
    const float* src = blockIdx.y ? LOC : GLO;
    __nv_bfloat16* hi = g_act + (long)(blockIdx.y * 2 + 0) * SQ * DIM;
    __nv_bfloat16* lo = g_act + (long)(blockIdx.y * 2 + 1) * SQ * DIM;
    long i = (long)blockIdx.x * 256 + threadIdx.x;
    float4 v = reinterpret_cast<const float4*>(src)[i];
    __nv_bfloat162 h0, l0, h1, l1;
    split2(v.x, v.y, h0, l0);
    split2(v.z, v.w, h1, l1);
    reinterpret_cast<__nv_bfloat162*>(hi)[i * 2]     = h0;
    reinterpret_cast<__nv_bfloat162*>(hi)[i * 2 + 1] = h1;
    reinterpret_cast<__nv_bfloat162*>(lo)[i * 2]     = l0;
    reinterpret_cast<__nv_bfloat162*>(lo)[i * 2 + 1] = l1;
}

__global__ __launch_bounds__(256)
void conv_w_kernel(const float* __restrict__ Wq, const float* __restrict__ Wk,
                   const float* __restrict__ Wv) {
    __shared__ float t[64][65];
    const int w = blockIdx.z, h = blockIdx.y, k0 = blockIdx.x * 64;
    const int tid = threadIdx.x;
    const float* W = ((w == 0) ? Wq : (w == 1) ? Wk : Wv) + (long)h * DIM * HDIM;
    #pragma unroll
    for (int it = 0; it < 4; it++) {
        int task = tid + it * 256;
        int k = task >> 4, n4 = (task & 15) * 4;
        float4 v = *reinterpret_cast<const float4*>(&W[(long)(k0 + k) * HDIM + n4]);
        t[k][n4] = v.x; t[k][n4 + 1] = v.y; t[k][n4 + 2] = v.z; t[k][n4 + 3] = v.w;
    }
    __syncthreads();
    __nv_bfloat16* dh = g_w_hi + (long)(w * NH + h) * HDIM * DIM + k0;
    __nv_bfloat16* dl = g_w_lo + (long)(w * NH + h) * HDIM * DIM + k0;
    #pragma unroll
    for (int it = 0; it < 8; it++) {
        int task = tid + it * 256;
        int n = task >> 5, k2 = (task & 31) * 2;
        __nv_bfloat162 h2, l2;
        split2(t[k2][n], t[k2 + 1][n], h2, l2);
        *reinterpret_cast<__nv_bfloat162*>(&dh[(long)n * DIM + k2]) = h2;
        *reinterpret_cast<__nv_bfloat162*>(&dl[(long)n * DIM + k2]) = l2;
    }
}

__global__ __launch_bounds__(256)
void conv_wo_kernel(const float* __restrict__ Wo) {
    __shared__ float t[64][65];
    const int k0 = blockIdx.x * 64, n0 = blockIdx.y * 64;
    const int tid = threadIdx.x;
    #pragma unroll
    for (int it = 0; it < 4; it++) {
        int task = tid + it * 256;
        int k = task >> 4, n4 = (task & 15) * 4;
        float4 v = *reinterpret_cast<const float4*>(&Wo[(long)(k0 + k) * DIM + n0 + n4]);
        t[k][n4] = v.x; t[k][n4 + 1] = v.y; t[k][n4 + 2] = v.z; t[k][n4 + 3] = v.w;
    }
    __syncthreads();
    #pragma unroll
    for (int it = 0; it < 8; it++) {
        int task = tid + it * 256;
        int n = task >> 5, k2 = (task & 31) * 2;
        __nv_bfloat162 h2, l2;
        split2(t[k2][n], t[k2 + 1][n], h2, l2);
        *reinterpret_cast<__nv_bfloat162*>(&g_wo_hi[(long)(n0 + n) * DIM + k0 + k2]) = h2;
        *reinterpret_cast<__nv_bfloat162*>(&g_wo_lo[(long)(n0 + n) * DIM + k0 + k2]) = l2;
    }
}

// ---------------- mma.sync bf16-split GEMM ---------------------------------
// 256 thr = 8 warps in 4x2 grid, 32x64 per warp. 2-stage cp.async.
// __launch_bounds__(256,2): regs<=128, smem 80KB -> 2 CTAs/SM.
#define ROWB        80
#define TEN_BYTES   (128 * ROWB)
#define STAGE_BYTES (4 * TEN_BYTES)
#define SM_MMA      (2 * STAGE_BYTES)   // 81920

__global__ __launch_bounds__(256, 2)
void mma_gemm_kernel(float* __restrict__ Cout, int mode) {
    extern __shared__ char smc[];
    const uint32_t sb = smem_u32(smc);
    const int tid = threadIdx.x;
    const int wid = tid >> 5, lane = tid & 31;
    const int wr = wid >> 1, wc = wid & 1;       // 4x2 warp grid (32m x 64n)
    const int m0 = blockIdx.x * 128;

    const __nv_bfloat16 *Ahi, *Alo, *Bhi, *Blo;
    float *C0f = nullptr, *C1f = nullptr;
    __nv_bfloat16 *C0h = nullptr, *C1h = nullptr, *C0l = nullptr, *C1l = nullptr;
    if (mode == 0) {
        const int z = blockIdx.z, hp = blockIdx.y;
        const int act = (z < 3) ? 0 : 1, w = (z < 3) ? z : z - 3;
        Ahi = g_act + (long)(act * 2 + 0) * SQ * DIM;
        Alo = g_act + (long)(act * 2 + 1) * SQ * DIM;
        Bhi = g_w_hi + (long)(w * NH + hp * 2) * HDIM * DIM;
        Blo = g_w_lo + (long)(w * NH + hp * 2) * HDIM * DIM;
        long coff = (long)z * NELEM + (long)(hp * 2) * SQ * HDIM + (long)m0 * HDIM;
        C0h = g_qkvh + coff; C1h = C0h + (long)SQ * HDIM;
        C0l = g_qkvl + coff; C1l = C0l + (long)SQ * HDIM;
    } else {
        const int z = blockIdx.z, n0 = blockIdx.y * 128;
        Ahi = g_ao + (long)(z * 2 + 0) * SQ * DIM;
        Alo = g_ao + (long)(z * 2 + 1) * SQ * DIM;
        Bhi = g_wo_hi + (long)n0 * DIM;
        Blo = g_wo_lo + (long)n0 * DIM;
        C0f = Cout + (long)z * SQ * DIM + (long)m0 * DIM + n0;
        C1f = C0f + 64;
    }

    const char* src[4] = {
        (const char*)(Ahi + (long)m0 * DIM), (const char*)(Alo + (long)m0 * DIM),
        (const char*)Bhi, (const char*)Blo };

    // A fragment addressing (warp row wr)
    const int aRow = wr * 32 + (lane & 7) + ((lane >> 3) & 1) * 8;
    const int aByte = aRow * ROWB + (lane >> 4) * 16;
    // B fragment addressing (warp col wc, np tile adds np*16 rows)
    const int bRow = wc * 64 + (lane & 7) + ((lane >> 4) & 1) * 8;
    const int bByte = bRow * ROWB + ((lane >> 3) & 1) * 16;

    float acc[2][8][4] = {};   // [mtile(16)][ntile(8)][frag]

    // prologue: chunk 0 -> stage 0 (each tensor: 512 x 16B tasks, 2 per thread)
    #pragma unroll
    for (int t = 0; t < 4; t++)
        #pragma unroll
        for (int it = 0; it < 2; it++) {
            int task = tid + it * 256;
            int r = task >> 2, cb = (task & 3) * 16;
            CP_ASYNC16(sb + t * TEN_BYTES + r * ROWB + cb,
                       src[t] + (long)r * 2048 + cb);
        }
    CP_COMMIT();

    for (int c = 0; c < 32; c++) {
        if (c + 1 < 32) {
            const uint32_t so = sb + ((c + 1) & 1) * STAGE_BYTES;
            const long go = (long)(c + 1) * 64;
            #pragma unroll
            for (int t = 0; t < 4; t++)
                #pragma unroll
                for (int it = 0; it < 2; it++) {
                    int task = tid + it * 256;
                    int r = task >> 2, cb = (task & 3) * 16;
                    CP_ASYNC16(so + t * TEN_BYTES + r * ROWB + cb,
                               src[t] + (long)r * 2048 + go + cb);
                }
            CP_COMMIT();
            CP_WAIT(1);
        } else {
            CP_WAIT(0);
        }
        __syncthreads();

        const uint32_t st = sb + (c & 1) * STAGE_BYTES;
        #pragma unroll
        for (int ks = 0; ks < 2; ks++) {
            uint32_t ah[2][4], al[2][4];
            #pragma unroll
            for (int mt = 0; mt < 2; mt++) {
                ldsm_x4(ah[mt], st + 0 * TEN_BYTES + aByte + mt * 16 * ROWB + ks * 32);
                ldsm_x4(al[mt], st + 1 * TEN_BYTES + aByte + mt * 16 * ROWB + ks * 32);
            }
            #pragma unroll
            for (int np = 0; np < 4; np++) {
                uint32_t bh[4], bl[4];
                ldsm_x4(bh, st + 2 * TEN_BYTES + bByte + np * 16 * ROWB + ks * 32);
                ldsm_x4(bl, st + 3 * TEN_BYTES + bByte + np * 16 * ROWB + ks * 32);
                #pragma unroll
                for (int mt = 0; mt < 2; mt++)
                    #pragma unroll
                    for (int ntl = 0; ntl < 2; ntl++) {
                        float* d = acc[mt][np * 2 + ntl];
                        mma16816(d, ah[mt], bh + ntl * 2);
                        mma16816(d, ah[mt], bl + ntl * 2);
                        mma16816(d, al[mt], bh + ntl * 2);
                    }
            }
        }
        __syncthreads();
    }

    const int rrel = wr * 32 + (lane >> 2);
    #pragma unroll
    for (int mt = 0; mt < 2; mt++)
        #pragma unroll
        for (int nt = 0; nt < 8; nt++) {
            int ncol = wc * 64 + nt * 8 + (lane & 3) * 2;
            int col = ncol & 63;
            long r0 = rrel + mt * 16, r1 = r0 + 8;
            if (mode == 0) {
                __nv_bfloat16* Ph = (ncol >= 64) ? C1h : C0h;
                __nv_bfloat16* Pl = (ncol >= 64) ? C1l : C0l;
                __nv_bfloat162 h2, l2;
                split2(acc[mt][nt][0], acc[mt][nt][1], h2, l2);
                *reinterpret_cast<uint32_t*>(&Ph[r0 * 64 + col]) = b2u(h2);
                *reinterpret_cast<uint32_t*>(&Pl[r0 * 64 + col]) = b2u(l2);
                split2(acc[mt][nt][2], acc[mt][nt][3], h2, l2);
                *reinterpret_cast<uint32_t*>(&Ph[r1 * 64 + col]) = b2u(h2);
                *reinterpret_cast<uint32_t*>(&Pl[r1 * 64 + col]) = b2u(l2);
            } else {
                float* P = (ncol >= 64) ? C1f : C0f;
                *reinterpret_cast<float2*>(&P[r0 * DIM + col]) =
                    make_float2(acc[mt][nt][0], acc[mt][nt][1]);
                *reinterpret_cast<float2*>(&P[r1 * DIM + col]) =
                    make_float2(acc[mt][nt][2], acc[mt][nt][3]);
            }
        }
}

// ---------------- mma.sync flash attention ---------------------------------
// 256 thr = 8 warps x 16 q-rows. 3-stage KV ring, ONE barrier per tile.
#define AT_Q   0
#define AT_KV  32768
#define AT_STG 32768
#define SMEMA  (32768 + 3 * 32768)   // 131072

__global__ __launch_bounds__(256)
void attn_kernel() {
    extern __shared__ char sma[];
    const uint32_t sb = smem_u32(sma);
    const int tid = threadIdx.x, lane = tid & 31, warp = tid >> 5;
    const int z = blockIdx.z, h = blockIdx.y, q0 = blockIdx.x * 128;

    const long hoff = (long)h * SQ * HDIM;
    const __nv_bfloat16* Qh_ = g_qkvh + (long)(z ? 3 : 0) * NELEM + hoff;
    const __nv_bfloat16* Ql_ = g_qkvl + (long)(z ? 3 : 0) * NELEM + hoff;
    const __nv_bfloat16* Kh_ = g_qkvh + (long)(z ? 1 : 4) * NELEM + hoff;
    const __nv_bfloat16* Kl_ = g_qkvl + (long)(z ? 1 : 4) * NELEM + hoff;
    const __nv_bfloat16* Vh_ = g_qkvh + (long)(z ? 2 : 5) * NELEM + hoff;
    const __nv_bfloat16* Vl_ = g_qkvl + (long)(z ? 2 : 5) * NELEM + hoff;
    __nv_bfloat16* AOhi = g_ao + (long)(z * 2 + 0) * SQ * DIM;
    __nv_bfloat16* AOlo = g_ao + (long)(z * 2 + 1) * SQ * DIM;

    // prologue: group0 = Q(hi+lo) + KV tile 0 -> stage 0; group1 = KV tile 1
    #pragma unroll
    for (int it = 0; it < 4; it++) {
        int task = tid + it * 256;
        int r = task >> 3, c = task & 7;
        uint32_t d = SWZ(r * 128 + c * 16);
        CP_ASYNC16(sb + AT_Q + d,         (const char*)(Qh_ + (long)(q0 + r) * 64) + c * 16);
        CP_ASYNC16(sb + AT_Q + 16384 + d, (const char*)(Ql_ + (long)(q0 + r) * 64) + c * 16);
    }
    #pragma unroll
    for (int it = 0; it < 2; it++) {
        int task = tid + it * 256;
        int r = task >> 3, c = task & 7;
        uint32_t d = SWZ(r * 128 + c * 16);
        const long g = (long)r * 64;
        CP_ASYNC16(sb + AT_KV + 0     + d, (const char*)(Kh_ + g) + c * 16);
        CP_ASYNC16(sb + AT_KV + 8192  + d, (const char*)(Kl_ + g) + c * 16);
        CP_ASYNC16(sb + AT_KV + 16384 + d, (const char*)(Vh_ + g) + c * 16);
        CP_ASYNC16(sb + AT_KV + 24576 + d, (const char*)(Vl_ + g) + c * 16);
    }
    CP_COMMIT();
    #pragma unroll
    for (int it = 0; it < 2; it++) {
        int task = tid + it * 256;
        int r = task >> 3, c = task & 7;
        uint32_t d = SWZ(r * 128 + c * 16);
        const long g = (long)(64 + r) * 64;
        CP_ASYNC16(sb + AT_KV + AT_STG + 0     + d, (const char*)(Kh_ + g) + c * 16);
        CP_ASYNC16(sb + AT_KV + AT_STG + 8192  + d, (const char*)(Kl_ + g) + c * 16);
        CP_ASYNC16(sb + AT_KV + AT_STG + 16384 + d, (const char*)(Vh_ + g) + c * 16);
        CP_ASYNC16(sb + AT_KV + AT_STG + 24576 + d, (const char*)(Vl_ + g) + c * 16);
    }
    CP_COMMIT();

    uint32_t qh[4][4], ql[4][4];
    float acc[8][4] = {};
    float m0 = -1e30f, m1 = -1e30f, l0 = 0.f, l1 = 0.f;
    const float scale = 0.125f;

    const int aRow = warp * 16 + (lane & 7) + ((lane >> 3) & 1) * 8;
    const int aC   = lane >> 4;
    const int kRowBase = (lane & 7) + ((lane >> 4) & 1) * 8;
    const int kC   = (lane >> 3) & 1;
    const int vRowBase = (lane & 7) + ((lane >> 3) & 1) * 8;
    const int vC   = lane >> 4;

    int sRead = 0, sWrite = 2;   // stage indices mod 3
    for (int j = 0; j < 32; j++) {
        CP_WAIT(1);          // group j complete (group j+1 may fly)
        __syncthreads();     // all threads see stage sRead (and Q on j==0)

        // issue KV tile j+2 into stage sWrite (freed at iter j-1)
        if (j + 2 < 32) {
            const uint32_t so = sb + AT_KV + sWrite * AT_STG;
            const long j2 = (long)(j + 2) * 64;
            #pragma unroll
            for (int it = 0; it < 2; it++) {
                int task = tid + it * 256;
                int r = task >> 3, c = task & 7;
                uint32_t d = SWZ(r * 128 + c * 16);
                const long g = (j2 + r) * 64;
                CP_ASYNC16(so + 0     + d, (const char*)(Kh_ + g) + c * 16);
                CP_ASYNC16(so + 8192  + d, (const char*)(Kl_ + g) + c * 16);
                CP_ASYNC16(so + 16384 + d, (const char*)(Vh_ + g) + c * 16);
                CP_ASYNC16(so + 24576 + d, (const char*)(Vl_ + g) + c * 16);
            }
        }
        CP_COMMIT();   // empty group when nothing issued keeps counting uniform

        if (j == 0) {
            #pragma unroll
            for (int kc = 0; kc < 4; kc++) {
                uint32_t ad = sb + AT_Q + SWZ(aRow * 128 + (kc * 2 + aC) * 16);
                ldsm_x4(qh[kc], ad);
                ldsm_x4(ql[kc], ad + 16384);
            }
        }

        const uint32_t kv = sb + AT_KV + sRead * AT_STG;

        // ---- S = Q K^T (3-term split) ------------------------------------
        float s[8][4] = {};
        #pragma unroll
        for (int nb = 0; nb < 4; nb++) {
            #pragma unroll
            for (int kc = 0; kc < 4; kc++) {
                uint32_t kh[4], kl[4];
                uint32_t ad = kv + SWZ((nb * 16 + kRowBase) * 128 + (kc * 2 + kC) * 16);
                ldsm_x4(kh, ad);
                ldsm_x4(kl, ad + 8192);
                mma16816(s[nb * 2],     qh[kc], kh);
                mma16816(s[nb * 2],     qh[kc], kl);
                mma16816(s[nb * 2],     ql[kc], kh);
                mma16816(s[nb * 2 + 1], qh[kc], kh + 2);
                mma16816(s[nb * 2 + 1], qh[kc], kl + 2);
                mma16816(s[nb * 2 + 1], ql[kc], kh + 2);
            }
        }

        // ---- online softmax ---------------------------------------------
        float mx0 = -1e30f, mx1 = -1e30f;
        #pragma unroll
        for (int nt = 0; nt < 8; nt++) {
            mx0 = fmaxf(mx0, fmaxf(s[nt][0], s[nt][1]));
            mx1 = fmaxf(mx1, fmaxf(s[nt][2], s[nt][3]));
        }
        #pragma unroll
        for (int off = 1; off <= 2; off <<= 1) {
            mx0 = fmaxf(mx0, __shfl_xor_sync(0xffffffffu, mx0, off));
            mx1 = fmaxf(mx1, __shfl_xor_sync(0xffffffffu, mx1, off));
        }
        float nm0 = fmaxf(m0, mx0 * scale), nm1 = fmaxf(m1, mx1 * scale);
        float cr0 = __expf(m0 - nm0), cr1 = __expf(m1 - nm1);
        m0 = nm0; m1 = nm1;

        uint32_t pah0[8], pal0[8], pah1[8], pal1[8];
        float rs0 = 0.f, rs1 = 0.f;
        #pragma unroll
        for (int nt = 0; nt < 8; nt++) {
            float p0 = __expf(s[nt][0] * scale - m0);
            float p1 = __expf(s[nt][1] * scale - m0);
            float p2 = __expf(s[nt][2] * scale - m1);
            float p3 = __expf(s[nt][3] * scale - m1);
            rs0 += p0 + p1; rs1 += p2 + p3;
            __nv_bfloat162 h2, l2;
            split2(p0, p1, h2, l2);
            pah0[nt] = b2u(h2); pal0[nt] = b2u(l2);
            split2(p2, p3, h2, l2);
            pah1[nt] = b2u(h2); pal1[nt] = b2u(l2);
        }
        #pragma unroll
        for (int off = 1; off <= 2; off <<= 1) {
            rs0 += __shfl_xor_sync(0xffffffffu, rs0, off);
            rs1 += __shfl_xor_sync(0xffffffffu, rs1, off);
        }
        l0 = l0 * cr0 + rs0;
        l1 = l1 * cr1 + rs1;
        #pragma unroll
        for (int nt = 0; nt < 8; nt++) {
            acc[nt][0] *= cr0; acc[nt][1] *= cr0;
            acc[nt][2] *= cr1; acc[nt][3] *= cr1;
        }

        // ---- acc += P V (3-term split) ----------------------------------
        #pragma unroll
        for (int nb = 0; nb < 4; nb++) {
            #pragma unroll
            for (int kc = 0; kc < 4; kc++) {
                uint32_t vh[4], vl[4];
                uint32_t ad = kv + 16384 +
                    SWZ((kc * 16 + vRowBase) * 128 + (nb * 2 + vC) * 16);
                ldsm_x4_t(vh, ad);
                ldsm_x4_t(vl, ad + 8192);
                uint32_t ah[4] = { pah0[2*kc], pah1[2*kc], pah0[2*kc+1], pah1[2*kc+1] };
                uint32_t al[4] = { pal0[2*kc], pal1[2*kc], pal0[2*kc+1], pal1[2*kc+1] };
                mma16816(acc[nb * 2],     ah, vh);
                mma16816(acc[nb * 2],     ah, vl);
                mma16816(acc[nb * 2],     al, vh);
                mma16816(acc[nb * 2 + 1], ah, vh + 2);
                mma16816(acc[nb * 2 + 1], ah, vl + 2);
                mma16816(acc[nb * 2 + 1], al, vh + 2);
            }
        }

        sRead  = (sRead  == 2) ? 0 : sRead + 1;
        sWrite = (sWrite == 2) ? 0 : sWrite + 1;
    }

    // ---- epilogue: normalize, split, store at flat [h][s][64] view --------
    const float inv0 = 1.0f / l0, inv1 = 1.0f / l1;
    const long r0 = q0 + warp * 16 + (lane >> 2);
    #pragma unroll
    for (int nt = 0; nt < 8; nt++) {
        int e = nt * 8 + (lane & 3) * 2;
        long i0 = (long)h * SQ * HDIM + r0 * HDIM + e;
        long i1 = i0 + 8L * HDIM;
        __nv_bfloat162 h2, l2;
        split2(acc[nt][0] * inv0, acc[nt][1] * inv0, h2, l2);
        *reinterpret_cast<uint32_t*>(&AOhi[i0]) = b2u(h2);
        *reinterpret_cast<uint32_t*>(&AOlo[i0]) = b2u(l2);
        split2(acc[nt][2] * inv1, acc[nt][3] * inv1, h2, l2);
        *reinterpret_cast<uint32_t*>(&AOhi[i1]) = b2u(h2);
        *reinterpret_cast<uint32_t*>(&AOlo[i1]) = b2u(l2);
    }
}

// ---------------- launch ----------------------------------------------------
extern "C" void kernel_launch(void* const* d_in, const int* in_sizes, int n_in,
                              void* d_out, int out_size) {
    const float* GLO = (const float*)d_in[0];
    const float* LOC = (const float*)d_in[1];
    const float* Wq  = (const float*)d_in[2];
    const float* Wk  = (const float*)d_in[3];
    const float* Wv  = (const float*)d_in[4];
    const float* Wo  = (const float*)d_in[5];
    float* out = (float*)d_out;

    cudaFuncSetAttribute(mma_gemm_kernel, cudaFuncAttributeMaxDynamicSharedMemorySize, SM_MMA);
    cudaFuncSetAttribute(attn_kernel, cudaFuncAttributeMaxDynamicSharedMemorySize, SMEMA);

    conv_act_kernel<<<dim3(2048, 2), 256>>>(GLO, LOC);
    conv_w_kernel<<<dim3(16, NH, 3), 256>>>(Wq, Wk, Wv);
    conv_wo_kernel<<<dim3(16, 16), 256>>>(Wo);

    mma_gemm_kernel<<<dim3(16, 8, 6), 256, SM_MMA>>>(out, 0);   // projections
    attn_kernel<<<dim3(16, NH, 2), 256, SMEMA>>>();
    mma_gemm_kernel<<<dim3(16, 8, 2), 256, SM_MMA>>>(out, 1);   // out-proj
}

// round 15
// speedup vs baseline: 4.4108x; 1.0736x over previous
#include <cuda_runtime.h>
#include <cuda_bf16.h>
#include <cstdint>
#include <math.h>

#define SQ   2048
#define DIM  1024
#define NH   16
#define HDIM 64
#define NELEM (NH * SQ * HDIM)   // elems per [H,S,HD] tensor

// ---------------- scratch (all __device__ globals; no allocs) --------------
__device__ __nv_bfloat16 g_qkvh[6L * NELEM];           // Q,K,V hi  [z][h][s][64]
__device__ __nv_bfloat16 g_qkvl[6L * NELEM];           // Q,K,V lo
__device__ __nv_bfloat16 g_act[4L * SQ * DIM];         // Ghi,Glo,Lhi,Llo
__device__ __nv_bfloat16 g_w_hi[3L * NH * HDIM * DIM]; // [w][h][n][k]
__device__ __nv_bfloat16 g_w_lo[3L * NH * HDIM * DIM];
__device__ __nv_bfloat16 g_wo_hi[(long)DIM * DIM];     // [n][k]
__device__ __nv_bfloat16 g_wo_lo[(long)DIM * DIM];
__device__ __nv_bfloat16 g_ao[4L * SQ * DIM];          // z0hi,z0lo,z1hi,z1lo

// ---------------- mma.sync / ldmatrix / cp.async helpers -------------------
__device__ __forceinline__ uint32_t smem_u32(const void* p) {
    uint32_t a;
    asm("{ .reg .u64 t; cvta.to.shared.u64 t, %1; cvt.u32.u64 %0, t; }"
        : "=r"(a) : "l"(p));
    return a;
}
__device__ __forceinline__ void mma16816(float* d, const uint32_t* a,
                                         const uint32_t* b) {
    asm volatile(
        "mma.sync.aligned.m16n8k16.row.col.f32.bf16.bf16.f32 "
        "{%0,%1,%2,%3}, {%4,%5,%6,%7}, {%8,%9}, {%0,%1,%2,%3};"
        : "+f"(d[0]), "+f"(d[1]), "+f"(d[2]), "+f"(d[3])
        : "r"(a[0]), "r"(a[1]), "r"(a[2]), "r"(a[3]), "r"(b[0]), "r"(b[1]));
}
__device__ __forceinline__ void ldsm_x4(uint32_t* r, uint32_t addr) {
    asm volatile("ldmatrix.sync.aligned.m8n8.x4.shared.b16 {%0,%1,%2,%3}, [%4];"
        : "=r"(r[0]), "=r"(r[1]), "=r"(r[2]), "=r"(r[3]) : "r"(addr));
}
__device__ __forceinline__ void ldsm_x4_t(uint32_t* r, uint32_t addr) {
    asm volatile("ldmatrix.sync.aligned.m8n8.x4.trans.shared.b16 {%0,%1,%2,%3}, [%4];"
        : "=r"(r[0]), "=r"(r[1]), "=r"(r[2]), "=r"(r[3]) : "r"(addr));
}
#define CP_ASYNC16(s, g) \
    asm volatile("cp.async.cg.shared.global [%0], [%1], 16;" :: "r"(s), "l"(g))
#define CP_COMMIT() asm volatile("cp.async.commit_group;" ::: "memory")
#define CP_WAIT(n)  asm volatile("cp.async.wait_group %0;" :: "n"(n) : "memory")
#define SWZ(off) ((off) ^ (((off) >> 3) & 0x70))

// ---------------- bf16 hi/lo split helper ----------------------------------
__device__ __forceinline__ void split2(float a, float b,
                                       __nv_bfloat162& h2, __nv_bfloat162& l2) {
    __nv_bfloat16 ha = __float2bfloat16(a), hb = __float2bfloat16(b);
    __nv_bfloat16 la = __float2bfloat16(a - __bfloat162float(ha));
    __nv_bfloat16 lb = __float2bfloat16(b - __bfloat162float(hb));
    h2 = __nv_bfloat162(ha, hb);
    l2 = __nv_bfloat162(la, lb);
}
__device__ __forceinline__ uint32_t b2u(__nv_bfloat162 v) {
    return *reinterpret_cast<uint32_t*>(&v);
}

// ---------------- convert kernels ------------------------------------------
__global__ __launch_bounds__(256)
void conv_act_kernel(const float* __restrict__ GLO, const float* __restrict__ LOC) {
    const float* src = blockIdx.y ? LOC : GLO;
    __nv_bfloat16* hi = g_act + (long)(blockIdx.y * 2 + 0) * SQ * DIM;
    __nv_bfloat16* lo = g_act + (long)(blockIdx.y * 2 + 1) * SQ * DIM;
    long i = (long)blockIdx.x * 256 + threadIdx.x;
    float4 v = reinterpret_cast<const float4*>(src)[i];
    __nv_bfloat162 h0, l0, h1, l1;
    split2(v.x, v.y, h0, l0);
    split2(v.z, v.w, h1, l1);
    reinterpret_cast<__nv_bfloat162*>(hi)[i * 2]     = h0;
    reinterpret_cast<__nv_bfloat162*>(hi)[i * 2 + 1] = h1;
    reinterpret_cast<__nv_bfloat162*>(lo)[i * 2]     = l0;
    reinterpret_cast<__nv_bfloat162*>(lo)[i * 2 + 1] = l1;
}

__global__ __launch_bounds__(256)
void conv_w_kernel(const float* __restrict__ Wq, const float* __restrict__ Wk,
                   const float* __restrict__ Wv) {
    __shared__ float t[64][65];
    const int w = blockIdx.z, h = blockIdx.y, k0 = blockIdx.x * 64;
    const int tid = threadIdx.x;
    const float* W = ((w == 0) ? Wq : (w == 1) ? Wk : Wv) + (long)h * DIM * HDIM;
    #pragma unroll
    for (int it = 0; it < 4; it++) {
        int task = tid + it * 256;
        int k = task >> 4, n4 = (task & 15) * 4;
        float4 v = *reinterpret_cast<const float4*>(&W[(long)(k0 + k) * HDIM + n4]);
        t[k][n4] = v.x; t[k][n4 + 1] = v.y; t[k][n4 + 2] = v.z; t[k][n4 + 3] = v.w;
    }
    __syncthreads();
    __nv_bfloat16* dh = g_w_hi + (long)(w * NH + h) * HDIM * DIM + k0;
    __nv_bfloat16* dl = g_w_lo + (long)(w * NH + h) * HDIM * DIM + k0;
    #pragma unroll
    for (int it = 0; it < 8; it++) {
        int task = tid + it * 256;
        int n = task >> 5, k2 = (task & 31) * 2;
        __nv_bfloat162 h2, l2;
        split2(t[k2][n], t[k2 + 1][n], h2, l2);
        *reinterpret_cast<__nv_bfloat162*>(&dh[(long)n * DIM + k2]) = h2;
        *reinterpret_cast<__nv_bfloat162*>(&dl[(long)n * DIM + k2]) = l2;
    }
}

__global__ __launch_bounds__(256)
void conv_wo_kernel(const float* __restrict__ Wo) {
    __shared__ float t[64][65];
    const int k0 = blockIdx.x * 64, n0 = blockIdx.y * 64;
    const int tid = threadIdx.x;
    #pragma unroll
    for (int it = 0; it < 4; it++) {
        int task = tid + it * 256;
        int k = task >> 4, n4 = (task & 15) * 4;
        float4 v = *reinterpret_cast<const float4*>(&Wo[(long)(k0 + k) * DIM + n0 + n4]);
        t[k][n4] = v.x; t[k][n4 + 1] = v.y; t[k][n4 + 2] = v.z; t[k][n4 + 3] = v.w;
    }
    __syncthreads();
    #pragma unroll
    for (int it = 0; it < 8; it++) {
        int task = tid + it * 256;
        int n = task >> 5, k2 = (task & 31) * 2;
        __nv_bfloat162 h2, l2;
        split2(t[k2][n], t[k2 + 1][n], h2, l2);
        *reinterpret_cast<__nv_bfloat162*>(&g_wo_hi[(long)(n0 + n) * DIM + k0 + k2]) = h2;
        *reinterpret_cast<__nv_bfloat162*>(&g_wo_lo[(long)(n0 + n) * DIM + k0 + k2]) = l2;
    }
}

// ---------------- mma.sync bf16-split GEMM (unchanged, 53% tensor) ---------
#define ROWB        80
#define TEN_BYTES   (128 * ROWB)
#define STAGE_BYTES (4 * TEN_BYTES)
#define SM_MMA      (2 * STAGE_BYTES)   // 81920

__global__ __launch_bounds__(256, 2)
void mma_gemm_kernel(float* __restrict__ Cout, int mode) {
    extern __shared__ char smc[];
    const uint32_t sb = smem_u32(smc);
    const int tid = threadIdx.x;
    const int wid = tid >> 5, lane = tid & 31;
    const int wr = wid >> 1, wc = wid & 1;       // 4x2 warp grid (32m x 64n)
    const int m0 = blockIdx.x * 128;

    const __nv_bfloat16 *Ahi, *Alo, *Bhi, *Blo;
    float *C0f = nullptr, *C1f = nullptr;
    __nv_bfloat16 *C0h = nullptr, *C1h = nullptr, *C0l = nullptr, *C1l = nullptr;
    if (mode == 0) {
        const int z = blockIdx.z, hp = blockIdx.y;
        const int act = (z < 3) ? 0 : 1, w = (z < 3) ? z : z - 3;
        Ahi = g_act + (long)(act * 2 + 0) * SQ * DIM;
        Alo = g_act + (long)(act * 2 + 1) * SQ * DIM;
        Bhi = g_w_hi + (long)(w * NH + hp * 2) * HDIM * DIM;
        Blo = g_w_lo + (long)(w * NH + hp * 2) * HDIM * DIM;
        long coff = (long)z * NELEM + (long)(hp * 2) * SQ * HDIM + (long)m0 * HDIM;
        C0h = g_qkvh + coff; C1h = C0h + (long)SQ * HDIM;
        C0l = g_qkvl + coff; C1l = C0l + (long)SQ * HDIM;
    } else {
        const int z = blockIdx.z, n0 = blockIdx.y * 128;
        Ahi = g_ao + (long)(z * 2 + 0) * SQ * DIM;
        Alo = g_ao + (long)(z * 2 + 1) * SQ * DIM;
        Bhi = g_wo_hi + (long)n0 * DIM;
        Blo = g_wo_lo + (long)n0 * DIM;
        C0f = Cout + (long)z * SQ * DIM + (long)m0 * DIM + n0;
        C1f = C0f + 64;
    }

    const char* src[4] = {
        (const char*)(Ahi + (long)m0 * DIM), (const char*)(Alo + (long)m0 * DIM),
        (const char*)Bhi, (const char*)Blo };

    const int aRow = wr * 32 + (lane & 7) + ((lane >> 3) & 1) * 8;
    const int aByte = aRow * ROWB + (lane >> 4) * 16;
    const int bRow = wc * 64 + (lane & 7) + ((lane >> 4) & 1) * 8;
    const int bByte = bRow * ROWB + ((lane >> 3) & 1) * 16;

    float acc[2][8][4] = {};

    #pragma unroll
    for (int t = 0; t < 4; t++)
        #pragma unroll
        for (int it = 0; it < 2; it++) {
            int task = tid + it * 256;
            int r = task >> 2, cb = (task & 3) * 16;
            CP_ASYNC16(sb + t * TEN_BYTES + r * ROWB + cb,
                       src[t] + (long)r * 2048 + cb);
        }
    CP_COMMIT();

    for (int c = 0; c < 32; c++) {
        if (c + 1 < 32) {
            const uint32_t so = sb + ((c + 1) & 1) * STAGE_BYTES;
            const long go = (long)(c + 1) * 64;
            #pragma unroll
            for (int t = 0; t < 4; t++)
                #pragma unroll
                for (int it = 0; it < 2; it++) {
                    int task = tid + it * 256;
                    int r = task >> 2, cb = (task & 3) * 16;
                    CP_ASYNC16(so + t * TEN_BYTES + r * ROWB + cb,
                               src[t] + (long)r * 2048 + go + cb);
                }
            CP_COMMIT();
            CP_WAIT(1);
        } else {
            CP_WAIT(0);
        }
        __syncthreads();

        const uint32_t st = sb + (c & 1) * STAGE_BYTES;
        #pragma unroll
        for (int ks = 0; ks < 2; ks++) {
            uint32_t ah[2][4], al[2][4];
            #pragma unroll
            for (int mt = 0; mt < 2; mt++) {
                ldsm_x4(ah[mt], st + 0 * TEN_BYTES + aByte + mt * 16 * ROWB + ks * 32);
                ldsm_x4(al[mt], st + 1 * TEN_BYTES + aByte + mt * 16 * ROWB + ks * 32);
            }
            #pragma unroll
            for (int np = 0; np < 4; np++) {
                uint32_t bh[4], bl[4];
                ldsm_x4(bh, st + 2 * TEN_BYTES + bByte + np * 16 * ROWB + ks * 32);
                ldsm_x4(bl, st + 3 * TEN_BYTES + bByte + np * 16 * ROWB + ks * 32);
                #pragma unroll
                for (int mt = 0; mt < 2; mt++)
                    #pragma unroll
                    for (int ntl = 0; ntl < 2; ntl++) {
                        float* d = acc[mt][np * 2 + ntl];
                        mma16816(d, ah[mt], bh + ntl * 2);
                        mma16816(d, ah[mt], bl + ntl * 2);
                        mma16816(d, al[mt], bh + ntl * 2);
                    }
            }
        }
        __syncthreads();
    }

    const int rrel = wr * 32 + (lane >> 2);
    #pragma unroll
    for (int mt = 0; mt < 2; mt++)
        #pragma unroll
        for (int nt = 0; nt < 8; nt++) {
            int ncol = wc * 64 + nt * 8 + (lane & 3) * 2;
            int col = ncol & 63;
            long r0 = rrel + mt * 16, r1 = r0 + 8;
            if (mode == 0) {
                __nv_bfloat16* Ph = (ncol >= 64) ? C1h : C0h;
                __nv_bfloat16* Pl = (ncol >= 64) ? C1l : C0l;
                __nv_bfloat162 h2, l2;
                split2(acc[mt][nt][0], acc[mt][nt][1], h2, l2);
                *reinterpret_cast<uint32_t*>(&Ph[r0 * 64 + col]) = b2u(h2);
                *reinterpret_cast<uint32_t*>(&Pl[r0 * 64 + col]) = b2u(l2);
                split2(acc[mt][nt][2], acc[mt][nt][3], h2, l2);
                *reinterpret_cast<uint32_t*>(&Ph[r1 * 64 + col]) = b2u(h2);
                *reinterpret_cast<uint32_t*>(&Pl[r1 * 64 + col]) = b2u(l2);
            } else {
                float* P = (ncol >= 64) ? C1f : C0f;
                *reinterpret_cast<float2*>(&P[r0 * DIM + col]) =
                    make_float2(acc[mt][nt][0], acc[mt][nt][1]);
                *reinterpret_cast<float2*>(&P[r1 * DIM + col]) =
                    make_float2(acc[mt][nt][2], acc[mt][nt][3]);
            }
        }
}

// ---------------- mma.sync flash attention ---------------------------------
// 256 thr = 8 warps x 16 q-rows. 2-stage KV ring, GEMM barrier pattern,
// Q fragments reloaded per tile (keeps regs <=128) -> 2 CTAs/SM.
#define AT_Q   0
#define AT_KV  32768
#define AT_STG 32768
#define SMEMA  (32768 + 2 * 32768)   // 98304

__global__ __launch_bounds__(256, 2)
void attn_kernel() {
    extern __shared__ char sma[];
    const uint32_t sb = smem_u32(sma);
    const int tid = threadIdx.x, lane = tid & 31, warp = tid >> 5;
    const int z = blockIdx.z, h = blockIdx.y, q0 = blockIdx.x * 128;

    const long hoff = (long)h * SQ * HDIM;
    const __nv_bfloat16* Qh_ = g_qkvh + (long)(z ? 3 : 0) * NELEM + hoff;
    const __nv_bfloat16* Ql_ = g_qkvl + (long)(z ? 3 : 0) * NELEM + hoff;
    const __nv_bfloat16* Kh_ = g_qkvh + (long)(z ? 1 : 4) * NELEM + hoff;
    const __nv_bfloat16* Kl_ = g_qkvl + (long)(z ? 1 : 4) * NELEM + hoff;
    const __nv_bfloat16* Vh_ = g_qkvh + (long)(z ? 2 : 5) * NELEM + hoff;
    const __nv_bfloat16* Vl_ = g_qkvl + (long)(z ? 2 : 5) * NELEM + hoff;
    __nv_bfloat16* AOhi = g_ao + (long)(z * 2 + 0) * SQ * DIM;
    __nv_bfloat16* AOlo = g_ao + (long)(z * 2 + 1) * SQ * DIM;

    // prologue group0: Q (hi+lo) + KV tile 0 -> stage 0
    #pragma unroll
    for (int it = 0; it < 4; it++) {
        int task = tid + it * 256;
        int r = task >> 3, c = task & 7;
        uint32_t d = SWZ(r * 128 + c * 16);
        CP_ASYNC16(sb + AT_Q + d,         (const char*)(Qh_ + (long)(q0 + r) * 64) + c * 16);
        CP_ASYNC16(sb + AT_Q + 16384 + d, (const char*)(Ql_ + (long)(q0 + r) * 64) + c * 16);
    }
    #pragma unroll
    for (int it = 0; it < 2; it++) {
        int task = tid + it * 256;
        int r = task >> 3, c = task & 7;
        uint32_t d = SWZ(r * 128 + c * 16);
        const long g = (long)r * 64;
        CP_ASYNC16(sb + AT_KV + 0     + d, (const char*)(Kh_ + g) + c * 16);
        CP_ASYNC16(sb + AT_KV + 8192  + d, (const char*)(Kl_ + g) + c * 16);
        CP_ASYNC16(sb + AT_KV + 16384 + d, (const char*)(Vh_ + g) + c * 16);
        CP_ASYNC16(sb + AT_KV + 24576 + d, (const char*)(Vl_ + g) + c * 16);
    }
    CP_COMMIT();

    float acc[8][4] = {};
    float m0 = -1e30f, m1 = -1e30f, l0 = 0.f, l1 = 0.f;
    const float scale = 0.125f;

    const int aRow = warp * 16 + (lane & 7) + ((lane >> 3) & 1) * 8;
    const int aC   = lane >> 4;
    const int kRowBase = (lane & 7) + ((lane >> 4) & 1) * 8;
    const int kC   = (lane >> 3) & 1;
    const int vRowBase = (lane & 7) + ((lane >> 3) & 1) * 8;
    const int vC   = lane >> 4;

    for (int j = 0; j < 32; j++) {
        if (j + 1 < 32) {
            const uint32_t so = sb + AT_KV + ((j + 1) & 1) * AT_STG;
            const long j1 = (long)(j + 1) * 64;
            #pragma unroll
            for (int it = 0; it < 2; it++) {
                int task = tid + it * 256;
                int r = task >> 3, c = task & 7;
                uint32_t d = SWZ(r * 128 + c * 16);
                const long g = (j1 + r) * 64;
                CP_ASYNC16(so + 0     + d, (const char*)(Kh_ + g) + c * 16);
                CP_ASYNC16(so + 8192  + d, (const char*)(Kl_ + g) + c * 16);
                CP_ASYNC16(so + 16384 + d, (const char*)(Vh_ + g) + c * 16);
                CP_ASYNC16(so + 24576 + d, (const char*)(Vl_ + g) + c * 16);
            }
            CP_COMMIT();
            CP_WAIT(1);
        } else {
            CP_WAIT(0);
        }
        __syncthreads();

        const uint32_t kv = sb + AT_KV + (j & 1) * AT_STG;

        // ---- Q fragments (reloaded per tile; phase-local registers) ------
        uint32_t qh[4][4], ql[4][4];
        #pragma unroll
        for (int kc = 0; kc < 4; kc++) {
            uint32_t ad = sb + AT_Q + SWZ(aRow * 128 + (kc * 2 + aC) * 16);
            ldsm_x4(qh[kc], ad);
            ldsm_x4(ql[kc], ad + 16384);
        }

        // ---- S = Q K^T (3-term split) ------------------------------------
        float s[8][4] = {};
        #pragma unroll
        for (int nb = 0; nb < 4; nb++) {
            #pragma unroll
            for (int kc = 0; kc < 4; kc++) {
                uint32_t kh[4], kl[4];
                uint32_t ad = kv + SWZ((nb * 16 + kRowBase) * 128 + (kc * 2 + kC) * 16);
                ldsm_x4(kh, ad);
                ldsm_x4(kl, ad + 8192);
                mma16816(s[nb * 2],     qh[kc], kh);
                mma16816(s[nb * 2],     qh[kc], kl);
                mma16816(s[nb * 2],     ql[kc], kh);
                mma16816(s[nb * 2 + 1], qh[kc], kh + 2);
                mma16816(s[nb * 2 + 1], qh[kc], kl + 2);
                mma16816(s[nb * 2 + 1], ql[kc], kh + 2);
            }
        }

        // ---- online softmax ---------------------------------------------
        float mx0 = -1e30f, mx1 = -1e30f;
        #pragma unroll
        for (int nt = 0; nt < 8; nt++) {
            mx0 = fmaxf(mx0, fmaxf(s[nt][0], s[nt][1]));
            mx1 = fmaxf(mx1, fmaxf(s[nt][2], s[nt][3]));
        }
        #pragma unroll
        for (int off = 1; off <= 2; off <<= 1) {
            mx0 = fmaxf(mx0, __shfl_xor_sync(0xffffffffu, mx0, off));
            mx1 = fmaxf(mx1, __shfl_xor_sync(0xffffffffu, mx1, off));
        }
        float nm0 = fmaxf(m0, mx0 * scale), nm1 = fmaxf(m1, mx1 * scale);
        float cr0 = __expf(m0 - nm0), cr1 = __expf(m1 - nm1);
        m0 = nm0; m1 = nm1;

        uint32_t pah0[8], pal0[8], pah1[8], pal1[8];
        float rs0 = 0.f, rs1 = 0.f;
        #pragma unroll
        for (int nt = 0; nt < 8; nt++) {
            float p0 = __expf(s[nt][0] * scale - m0);
            float p1 = __expf(s[nt][1] * scale - m0);
            float p2 = __expf(s[nt][2] * scale - m1);
            float p3 = __expf(s[nt][3] * scale - m1);
            rs0 += p0 + p1; rs1 += p2 + p3;
            __nv_bfloat162 h2, l2;
            split2(p0, p1, h2, l2);
            pah0[nt] = b2u(h2); pal0[nt] = b2u(l2);
            split2(p2, p3, h2, l2);
            pah1[nt] = b2u(h2); pal1[nt] = b2u(l2);
        }
        #pragma unroll
        for (int off = 1; off <= 2; off <<= 1) {
            rs0 += __shfl_xor_sync(0xffffffffu, rs0, off);
            rs1 += __shfl_xor_sync(0xffffffffu, rs1, off);
        }
        l0 = l0 * cr0 + rs0;
        l1 = l1 * cr1 + rs1;
        #pragma unroll
        for (int nt = 0; nt < 8; nt++) {
            acc[nt][0] *= cr0; acc[nt][1] *= cr0;
            acc[nt][2] *= cr1; acc[nt][3] *= cr1;
        }

        // ---- acc += P V (3-term split) ----------------------------------
        #pragma unroll
        for (int nb = 0; nb < 4; nb++) {
            #pragma unroll
            for (int kc = 0; kc < 4; kc++) {
                uint32_t vh[4], vl[4];
                uint32_t ad = kv + 16384 +
                    SWZ((kc * 16 + vRowBase) * 128 + (nb * 2 + vC) * 16);
                ldsm_x4_t(vh, ad);
                ldsm_x4_t(vl, ad + 8192);
                uint32_t ah[4] = { pah0[2*kc], pah1[2*kc], pah0[2*kc+1], pah1[2*kc+1] };
                uint32_t al[4] = { pal0[2*kc], pal1[2*kc], pal0[2*kc+1], pal1[2*kc+1] };
                mma16816(acc[nb * 2],     ah, vh);
                mma16816(acc[nb * 2],     ah, vl);
                mma16816(acc[nb * 2],     al, vh);
                mma16816(acc[nb * 2 + 1], ah, vh + 2);
                mma16816(acc[nb * 2 + 1], ah, vl + 2);
                mma16816(acc[nb * 2 + 1], al, vh + 2);
            }
        }
        __syncthreads();   // all reads of stage j&1 done before next issue
    }

    // ---- epilogue: normalize, split, store at flat [h][s][64] view --------
    const float inv0 = 1.0f / l0, inv1 = 1.0f / l1;
    const long r0 = q0 + warp * 16 + (lane >> 2);
    #pragma unroll
    for (int nt = 0; nt < 8; nt++) {
        int e = nt * 8 + (lane & 3) * 2;
        long i0 = (long)h * SQ * HDIM + r0 * HDIM + e;
        long i1 = i0 + 8L * HDIM;
        __nv_bfloat162 h2, l2;
        split2(acc[nt][0] * inv0, acc[nt][1] * inv0, h2, l2);
        *reinterpret_cast<uint32_t*>(&AOhi[i0]) = b2u(h2);
        *reinterpret_cast<uint32_t*>(&AOlo[i0]) = b2u(l2);
        split2(acc[nt][2] * inv1, acc[nt][3] * inv1, h2, l2);
        *reinterpret_cast<uint32_t*>(&AOhi[i1]) = b2u(h2);
        *reinterpret_cast<uint32_t*>(&AOlo[i1]) = b2u(l2);
    }
}

// ---------------- launch ----------------------------------------------------
extern "C" void kernel_launch(void* const* d_in, const int* in_sizes, int n_in,
                              void* d_out, int out_size) {
    const float* GLO = (const float*)d_in[0];
    const float* LOC = (const float*)d_in[1];
    const float* Wq  = (const float*)d_in[2];
    const float* Wk  = (const float*)d_in[3];
    const float* Wv  = (const float*)d_in[4];
    const float* Wo  = (const float*)d_in[5];
    float* out = (float*)d_out;

    cudaFuncSetAttribute(mma_gemm_kernel, cudaFuncAttributeMaxDynamicSharedMemorySize, SM_MMA);
    cudaFuncSetAttribute(attn_kernel, cudaFuncAttributeMaxDynamicSharedMemorySize, SMEMA);

    conv_act_kernel<<<dim3(2048, 2), 256>>>(GLO, LOC);
    conv_w_kernel<<<dim3(16, NH, 3), 256>>>(Wq, Wk, Wv);
    conv_wo_kernel<<<dim3(16, 16), 256>>>(Wo);

    mma_gemm_kernel<<<dim3(16, 8, 6), 256, SM_MMA>>>(out, 0);   // projections
    attn_kernel<<<dim3(16, NH, 2), 256, SMEMA>>>();
    mma_gemm_kernel<<<dim3(16, 8, 2), 256, SM_MMA>>>(out, 1);   // out-proj
}

// round 16
// speedup vs baseline: 4.4540x; 1.0098x over previous
#include <cuda_runtime.h>
#include <cuda_bf16.h>
#include <cstdint>
#include <math.h>

#define SQ   2048
#define DIM  1024
#define NH   16
#define HDIM 64
#define NELEM (NH * SQ * HDIM)   // elems per [H,S,HD] tensor

// ---------------- scratch (all __device__ globals; no allocs) --------------
__device__ __nv_bfloat16 g_qkvh[6L * NELEM];           // Q,K,V hi  [z][h][s][64]
__device__ __nv_bfloat16 g_qkvl[6L * NELEM];           // Q,K,V lo
__device__ __nv_bfloat16 g_act[4L * SQ * DIM];         // Ghi,Glo,Lhi,Llo
__device__ __nv_bfloat16 g_w_hi[3L * NH * HDIM * DIM]; // [w][h][n][k]
__device__ __nv_bfloat16 g_w_lo[3L * NH * HDIM * DIM];
__device__ __nv_bfloat16 g_wo_hi[(long)DIM * DIM];     // [n][k]
__device__ __nv_bfloat16 g_wo_lo[(long)DIM * DIM];
__device__ __nv_bfloat16 g_ao[4L * SQ * DIM];          // z0hi,z0lo,z1hi,z1lo

// ---------------- mma.sync / ldmatrix / cp.async helpers -------------------
__device__ __forceinline__ uint32_t smem_u32(const void* p) {
    uint32_t a;
    asm("{ .reg .u64 t; cvta.to.shared.u64 t, %1; cvt.u32.u64 %0, t; }"
        : "=r"(a) : "l"(p));
    return a;
}
__device__ __forceinline__ void mma16816(float* d, const uint32_t* a,
                                         const uint32_t* b) {
    asm volatile(
        "mma.sync.aligned.m16n8k16.row.col.f32.bf16.bf16.f32 "
        "{%0,%1,%2,%3}, {%4,%5,%6,%7}, {%8,%9}, {%0,%1,%2,%3};"
        : "+f"(d[0]), "+f"(d[1]), "+f"(d[2]), "+f"(d[3])
        : "r"(a[0]), "r"(a[1]), "r"(a[2]), "r"(a[3]), "r"(b[0]), "r"(b[1]));
}
__device__ __forceinline__ void ldsm_x4(uint32_t* r, uint32_t addr) {
    asm volatile("ldmatrix.sync.aligned.m8n8.x4.shared.b16 {%0,%1,%2,%3}, [%4];"
        : "=r"(r[0]), "=r"(r[1]), "=r"(r[2]), "=r"(r[3]) : "r"(addr));
}
__device__ __forceinline__ void ldsm_x4_t(uint32_t* r, uint32_t addr) {
    asm volatile("ldmatrix.sync.aligned.m8n8.x4.trans.shared.b16 {%0,%1,%2,%3}, [%4];"
        : "=r"(r[0]), "=r"(r[1]), "=r"(r[2]), "=r"(r[3]) : "r"(addr));
}
#define CP_ASYNC16(s, g) \
    asm volatile("cp.async.cg.shared.global [%0], [%1], 16;" :: "r"(s), "l"(g))
#define CP_COMMIT() asm volatile("cp.async.commit_group;" ::: "memory")
#define CP_WAIT(n)  asm volatile("cp.async.wait_group %0;" :: "n"(n) : "memory")
#define SWZ(off) ((off) ^ (((off) >> 3) & 0x70))

// ---------------- bf16 hi/lo split helper ----------------------------------
__device__ __forceinline__ void split2(float a, float b,
                                       __nv_bfloat162& h2, __nv_bfloat162& l2) {
    __nv_bfloat16 ha = __float2bfloat16(a), hb = __float2bfloat16(b);
    __nv_bfloat16 la = __float2bfloat16(a - __bfloat162float(ha));
    __nv_bfloat16 lb = __float2bfloat16(b - __bfloat162float(hb));
    h2 = __nv_bfloat162(ha, hb);
    l2 = __nv_bfloat162(la, lb);
}
__device__ __forceinline__ uint32_t b2u(__nv_bfloat162 v) {
    return *reinterpret_cast<uint32_t*>(&v);
}

// ---------------- fused convert kernel (one launch) ------------------------
// blocks [0,4096): act split; [4096,4864): W q/k/v; [4864,5120): Wo.
__global__ __launch_bounds__(256)
void conv_all_kernel(const float* __restrict__ GLO, const float* __restrict__ LOC,
                     const float* __restrict__ Wq, const float* __restrict__ Wk,
                     const float* __restrict__ Wv, const float* __restrict__ Wo) {
    __shared__ float t[64][65];
    const int b = blockIdx.x;
    const int tid = threadIdx.x;

    if (b < 4096) {
        const int y = b >> 11, x = b & 2047;
        const float* src = y ? LOC : GLO;
        __nv_bfloat16* hi = g_act + (long)(y * 2 + 0) * SQ * DIM;
        __nv_bfloat16* lo = g_act + (long)(y * 2 + 1) * SQ * DIM;
        long i = (long)x * 256 + tid;
        float4 v = reinterpret_cast<const float4*>(src)[i];
        __nv_bfloat162 h0, l0, h1, l1;
        split2(v.x, v.y, h0, l0);
        split2(v.z, v.w, h1, l1);
        reinterpret_cast<__nv_bfloat162*>(hi)[i * 2]     = h0;
        reinterpret_cast<__nv_bfloat162*>(hi)[i * 2 + 1] = h1;
        reinterpret_cast<__nv_bfloat162*>(lo)[i * 2]     = l0;
        reinterpret_cast<__nv_bfloat162*>(lo)[i * 2 + 1] = l1;
    } else if (b < 4864) {
        const int idx = b - 4096;
        const int k0 = (idx & 15) * 64, h = (idx >> 4) & 15, w = idx >> 8;
        const float* W = ((w == 0) ? Wq : (w == 1) ? Wk : Wv) + (long)h * DIM * HDIM;
        #pragma unroll
        for (int it = 0; it < 4; it++) {
            int task = tid + it * 256;
            int k = task >> 4, n4 = (task & 15) * 4;
            float4 v = *reinterpret_cast<const float4*>(&W[(long)(k0 + k) * HDIM + n4]);
            t[k][n4] = v.x; t[k][n4 + 1] = v.y; t[k][n4 + 2] = v.z; t[k][n4 + 3] = v.w;
        }
        __syncthreads();
        __nv_bfloat16* dh = g_w_hi + (long)(w * NH + h) * HDIM * DIM + k0;
        __nv_bfloat16* dl = g_w_lo + (long)(w * NH + h) * HDIM * DIM + k0;
        #pragma unroll
        for (int it = 0; it < 8; it++) {
            int task = tid + it * 256;
            int n = task >> 5, k2 = (task & 31) * 2;
            __nv_bfloat162 h2, l2;
            split2(t[k2][n], t[k2 + 1][n], h2, l2);
            *reinterpret_cast<__nv_bfloat162*>(&dh[(long)n * DIM + k2]) = h2;
            *reinterpret_cast<__nv_bfloat162*>(&dl[(long)n * DIM + k2]) = l2;
        }
    } else {
        const int idx = b - 4864;
        const int k0 = (idx & 15) * 64, n0 = (idx >> 4) * 64;
        #pragma unroll
        for (int it = 0; it < 4; it++) {
            int task = tid + it * 256;
            int k = task >> 4, n4 = (task & 15) * 4;
            float4 v = *reinterpret_cast<const float4*>(&Wo[(long)(k0 + k) * DIM + n0 + n4]);
            t[k][n4] = v.x; t[k][n4 + 1] = v.y; t[k][n4 + 2] = v.z; t[k][n4 + 3] = v.w;
        }
        __syncthreads();
        #pragma unroll
        for (int it = 0; it < 8; it++) {
            int task = tid + it * 256;
            int n = task >> 5, k2 = (task & 31) * 2;
            __nv_bfloat162 h2, l2;
            split2(t[k2][n], t[k2 + 1][n], h2, l2);
            *reinterpret_cast<__nv_bfloat162*>(&g_wo_hi[(long)(n0 + n) * DIM + k0 + k2]) = h2;
            *reinterpret_cast<__nv_bfloat162*>(&g_wo_lo[(long)(n0 + n) * DIM + k0 + k2]) = l2;
        }
    }
}

// ---------------- mma.sync bf16-split GEMM ---------------------------------
// 256 thr = 8 warps in 4x2 grid, 32x64 per warp.
// 3-stage cp.async ring, ONE __syncthreads per chunk.
// Stage layout: [Ahi 128x80][Bhi 128x80][Alo 128x64 swz][Blo 128x64 swz].
#define AHI_OFF 0
#define BHI_OFF 10240
#define ALO_OFF 20480
#define BLO_OFF 28672
#define STG_B   36864
#define SM_MMA  (3 * STG_B)   // 110592 -> 2 CTAs/SM

__global__ __launch_bounds__(256, 2)
void mma_gemm_kernel(float* __restrict__ Cout, int mode) {
    extern __shared__ char smc[];
    const uint32_t sb = smem_u32(smc);
    const int tid = threadIdx.x;
    const int wid = tid >> 5, lane = tid & 31;
    const int wr = wid >> 1, wc = wid & 1;       // 4x2 warp grid (32m x 64n)
    const int m0 = blockIdx.x * 128;

    const __nv_bfloat16 *Ahi, *Alo, *Bhi, *Blo;
    float *C0f = nullptr, *C1f = nullptr;
    __nv_bfloat16 *C0h = nullptr, *C1h = nullptr, *C0l = nullptr, *C1l = nullptr;
    if (mode == 0) {
        const int z = blockIdx.z, hp = blockIdx.y;
        const int act = (z < 3) ? 0 : 1, w = (z < 3) ? z : z - 3;
        Ahi = g_act + (long)(act * 2 + 0) * SQ * DIM;
        Alo = g_act + (long)(act * 2 + 1) * SQ * DIM;
        Bhi = g_w_hi + (long)(w * NH + hp * 2) * HDIM * DIM;
        Blo = g_w_lo + (long)(w * NH + hp * 2) * HDIM * DIM;
        long coff = (long)z * NELEM + (long)(hp * 2) * SQ * HDIM + (long)m0 * HDIM;
        C0h = g_qkvh + coff; C1h = C0h + (long)SQ * HDIM;
        C0l = g_qkvl + coff; C1l = C0l + (long)SQ * HDIM;
    } else {
        const int z = blockIdx.z, n0 = blockIdx.y * 128;
        Ahi = g_ao + (long)(z * 2 + 0) * SQ * DIM;
        Alo = g_ao + (long)(z * 2 + 1) * SQ * DIM;
        Bhi = g_wo_hi + (long)n0 * DIM;
        Blo = g_wo_lo + (long)n0 * DIM;
        C0f = Cout + (long)z * SQ * DIM + (long)m0 * DIM + n0;
        C1f = C0f + 64;
    }

    const char* Ah = (const char*)(Ahi + (long)m0 * DIM);
    const char* Al = (const char*)(Alo + (long)m0 * DIM);
    const char* Bh = (const char*)Bhi;
    const char* Bl = (const char*)Blo;

    auto issue_chunk = [&](int chunk, uint32_t stg) {
        const long go = (long)chunk * 64;   // 32 k-elems = 64 bytes
        #pragma unroll
        for (int it = 0; it < 2; it++) {
            int task = tid + it * 256;
            int r = task >> 2, cq = task & 3;
            int cb = cq * 16;
            int cs = ((cq ^ (r & 3)) << 4);   // lo-tensor XOR swizzle
            CP_ASYNC16(stg + AHI_OFF + r * 80 + cb, Ah + (long)r * 2048 + go + cb);
            CP_ASYNC16(stg + BHI_OFF + r * 80 + cb, Bh + (long)r * 2048 + go + cb);
            CP_ASYNC16(stg + ALO_OFF + r * 64 + cs, Al + (long)r * 2048 + go + cb);
            CP_ASYNC16(stg + BLO_OFF + r * 64 + cs, Bl + (long)r * 2048 + go + cb);
        }
    };

    // prologue: chunks 0,1 into stages 0,1
    issue_chunk(0, sb);
    CP_COMMIT();
    issue_chunk(1, sb + STG_B);
    CP_COMMIT();

    const int aRow  = wr * 32 + (lane & 7) + ((lane >> 3) & 1) * 8;
    const int aHalf = lane >> 4;
    const int bRow  = wc * 64 + (lane & 7) + ((lane >> 4) & 1) * 8;
    const int bHalf = (lane >> 3) & 1;
    const int aSw   = aRow & 3;
    const int bSw   = bRow & 3;

    float acc[2][8][4] = {};

    int sRead = 0, sWrite = 2;
    for (int c = 0; c < 32; c++) {
        if (c < 31) { CP_WAIT(1); } else { CP_WAIT(0); }
        __syncthreads();   // stage sRead visible; stage sWrite's readers done
        if (c + 2 < 32) {
            issue_chunk(c + 2, sb + sWrite * STG_B);
            CP_COMMIT();
        }

        const uint32_t st = sb + sRead * STG_B;
        #pragma unroll
        for (int ks = 0; ks < 2; ks++) {
            uint32_t ah[2][4], al[2][4];
            const int caLo = ((ks * 2 + aHalf) ^ aSw) << 4;
            #pragma unroll
            for (int mt = 0; mt < 2; mt++) {
                ldsm_x4(ah[mt], st + AHI_OFF + (aRow + mt * 16) * 80 + ks * 32 + aHalf * 16);
                ldsm_x4(al[mt], st + ALO_OFF + (aRow + mt * 16) * 64 + caLo);
            }
            const int cbLo = ((ks * 2 + bHalf) ^ bSw) << 4;
            #pragma unroll
            for (int np = 0; np < 4; np++) {
                uint32_t bh[4], bl[4];
                ldsm_x4(bh, st + BHI_OFF + (bRow + np * 16) * 80 + ks * 32 + bHalf * 16);
                ldsm_x4(bl, st + BLO_OFF + (bRow + np * 16) * 64 + cbLo);
                #pragma unroll
                for (int mt = 0; mt < 2; mt++)
                    #pragma unroll
                    for (int ntl = 0; ntl < 2; ntl++) {
                        float* d = acc[mt][np * 2 + ntl];
                        mma16816(d, ah[mt], bh + ntl * 2);
                        mma16816(d, ah[mt], bl + ntl * 2);
                        mma16816(d, al[mt], bh + ntl * 2);
                    }
            }
        }
        sRead  = (sRead  == 2) ? 0 : sRead + 1;
        sWrite = (sWrite == 2) ? 0 : sWrite + 1;
    }

    const int rrel = wr * 32 + (lane >> 2);
    #pragma unroll
    for (int mt = 0; mt < 2; mt++)
        #pragma unroll
        for (int nt = 0; nt < 8; nt++) {
            int ncol = wc * 64 + nt * 8 + (lane & 3) * 2;
            int col = ncol & 63;
            long r0 = rrel + mt * 16, r1 = r0 + 8;
            if (mode == 0) {
                __nv_bfloat16* Ph = (ncol >= 64) ? C1h : C0h;
                __nv_bfloat16* Pl = (ncol >= 64) ? C1l : C0l;
                __nv_bfloat162 h2, l2;
                split2(acc[mt][nt][0], acc[mt][nt][1], h2, l2);
                *reinterpret_cast<uint32_t*>(&Ph[r0 * 64 + col]) = b2u(h2);
                *reinterpret_cast<uint32_t*>(&Pl[r0 * 64 + col]) = b2u(l2);
                split2(acc[mt][nt][2], acc[mt][nt][3], h2, l2);
                *reinterpret_cast<uint32_t*>(&Ph[r1 * 64 + col]) = b2u(h2);
                *reinterpret_cast<uint32_t*>(&Pl[r1 * 64 + col]) = b2u(l2);
            } else {
                float* P = (ncol >= 64) ? C1f : C0f;
                *reinterpret_cast<float2*>(&P[r0 * DIM + col]) =
                    make_float2(acc[mt][nt][0], acc[mt][nt][1]);
                *reinterpret_cast<float2*>(&P[r1 * DIM + col]) =
                    make_float2(acc[mt][nt][2], acc[mt][nt][3]);
            }
        }
}

// ---------------- mma.sync flash attention (unchanged from round 15) -------
#define AT_Q   0
#define AT_KV  32768
#define AT_STG 32768
#define SMEMA  (32768 + 2 * 32768)   // 98304

__global__ __launch_bounds__(256, 2)
void attn_kernel() {
    extern __shared__ char sma[];
    const uint32_t sb = smem_u32(sma);
    const int tid = threadIdx.x, lane = tid & 31, warp = tid >> 5;
    const int z = blockIdx.z, h = blockIdx.y, q0 = blockIdx.x * 128;

    const long hoff = (long)h * SQ * HDIM;
    const __nv_bfloat16* Qh_ = g_qkvh + (long)(z ? 3 : 0) * NELEM + hoff;
    const __nv_bfloat16* Ql_ = g_qkvl + (long)(z ? 3 : 0) * NELEM + hoff;
    const __nv_bfloat16* Kh_ = g_qkvh + (long)(z ? 1 : 4) * NELEM + hoff;
    const __nv_bfloat16* Kl_ = g_qkvl + (long)(z ? 1 : 4) * NELEM + hoff;
    const __nv_bfloat16* Vh_ = g_qkvh + (long)(z ? 2 : 5) * NELEM + hoff;
    const __nv_bfloat16* Vl_ = g_qkvl + (long)(z ? 2 : 5) * NELEM + hoff;
    __nv_bfloat16* AOhi = g_ao + (long)(z * 2 + 0) * SQ * DIM;
    __nv_bfloat16* AOlo = g_ao + (long)(z * 2 + 1) * SQ * DIM;

    #pragma unroll
    for (int it = 0; it < 4; it++) {
        int task = tid + it * 256;
        int r = task >> 3, c = task & 7;
        uint32_t d = SWZ(r * 128 + c * 16);
        CP_ASYNC16(sb + AT_Q + d,         (const char*)(Qh_ + (long)(q0 + r) * 64) + c * 16);
        CP_ASYNC16(sb + AT_Q + 16384 + d, (const char*)(Ql_ + (long)(q0 + r) * 64) + c * 16);
    }
    #pragma unroll
    for (int it = 0; it < 2; it++) {
        int task = tid + it * 256;
        int r = task >> 3, c = task & 7;
        uint32_t d = SWZ(r * 128 + c * 16);
        const long g = (long)r * 64;
        CP_ASYNC16(sb + AT_KV + 0     + d, (const char*)(Kh_ + g) + c * 16);
        CP_ASYNC16(sb + AT_KV + 8192  + d, (const char*)(Kl_ + g) + c * 16);
        CP_ASYNC16(sb + AT_KV + 16384 + d, (const char*)(Vh_ + g) + c * 16);
        CP_ASYNC16(sb + AT_KV + 24576 + d, (const char*)(Vl_ + g) + c * 16);
    }
    CP_COMMIT();

    float acc[8][4] = {};
    float m0 = -1e30f, m1 = -1e30f, l0 = 0.f, l1 = 0.f;
    const float scale = 0.125f;

    const int aRow = warp * 16 + (lane & 7) + ((lane >> 3) & 1) * 8;
    const int aC   = lane >> 4;
    const int kRowBase = (lane & 7) + ((lane >> 4) & 1) * 8;
    const int kC   = (lane >> 3) & 1;
    const int vRowBase = (lane & 7) + ((lane >> 3) & 1) * 8;
    const int vC   = lane >> 4;

    for (int j = 0; j < 32; j++) {
        if (j + 1 < 32) {
            const uint32_t so = sb + AT_KV + ((j + 1) & 1) * AT_STG;
            const long j1 = (long)(j + 1) * 64;
            #pragma unroll
            for (int it = 0; it < 2; it++) {
                int task = tid + it * 256;
                int r = task >> 3, c = task & 7;
                uint32_t d = SWZ(r * 128 + c * 16);
                const long g = (j1 + r) * 64;
                CP_ASYNC16(so + 0     + d, (const char*)(Kh_ + g) + c * 16);
                CP_ASYNC16(so + 8192  + d, (const char*)(Kl_ + g) + c * 16);
                CP_ASYNC16(so + 16384 + d, (const char*)(Vh_ + g) + c * 16);
                CP_ASYNC16(so + 24576 + d, (const char*)(Vl_ + g) + c * 16);
            }
            CP_COMMIT();
            CP_WAIT(1);
        } else {
            CP_WAIT(0);
        }
        __syncthreads();

        const uint32_t kv = sb + AT_KV + (j & 1) * AT_STG;

        uint32_t qh[4][4], ql[4][4];
        #pragma unroll
        for (int kc = 0; kc < 4; kc++) {
            uint32_t ad = sb + AT_Q + SWZ(aRow * 128 + (kc * 2 + aC) * 16);
            ldsm_x4(qh[kc], ad);
            ldsm_x4(ql[kc], ad + 16384);
        }

        float s[8][4] = {};
        #pragma unroll
        for (int nb = 0; nb < 4; nb++) {
            #pragma unroll
            for (int kc = 0; kc < 4; kc++) {
                uint32_t kh[4], kl[4];
                uint32_t ad = kv + SWZ((nb * 16 + kRowBase) * 128 + (kc * 2 + kC) * 16);
                ldsm_x4(kh, ad);
                ldsm_x4(kl, ad + 8192);
                mma16816(s[nb * 2],     qh[kc], kh);
                mma16816(s[nb * 2],     qh[kc], kl);
                mma16816(s[nb * 2],     ql[kc], kh);
                mma16816(s[nb * 2 + 1], qh[kc], kh + 2);
                mma16816(s[nb * 2 + 1], qh[kc], kl + 2);
                mma16816(s[nb * 2 + 1], ql[kc], kh + 2);
            }
        }

        float mx0 = -1e30f, mx1 = -1e30f;
        #pragma unroll
        for (int nt = 0; nt < 8; nt++) {
            mx0 = fmaxf(mx0, fmaxf(s[nt][0], s[nt][1]));
            mx1 = fmaxf(mx1, fmaxf(s[nt][2], s[nt][3]));
        }
        #pragma unroll
        for (int off = 1; off <= 2; off <<= 1) {
            mx0 = fmaxf(mx0, __shfl_xor_sync(0xffffffffu, mx0, off));
            mx1 = fmaxf(mx1, __shfl_xor_sync(0xffffffffu, mx1, off));
        }
        float nm0 = fmaxf(m0, mx0 * scale), nm1 = fmaxf(m1, mx1 * scale);
        float cr0 = __expf(m0 - nm0), cr1 = __expf(m1 - nm1);
        m0 = nm0; m1 = nm1;

        uint32_t pah0[8], pal0[8], pah1[8], pal1[8];
        float rs0 = 0.f, rs1 = 0.f;
        #pragma unroll
        for (int nt = 0; nt < 8; nt++) {
            float p0 = __expf(s[nt][0] * scale - m0);
            float p1 = __expf(s[nt][1] * scale - m0);
            float p2 = __expf(s[nt][2] * scale - m1);
            float p3 = __expf(s[nt][3] * scale - m1);
            rs0 += p0 + p1; rs1 += p2 + p3;
            __nv_bfloat162 h2, l2;
            split2(p0, p1, h2, l2);
            pah0[nt] = b2u(h2); pal0[nt] = b2u(l2);
            split2(p2, p3, h2, l2);
            pah1[nt] = b2u(h2); pal1[nt] = b2u(l2);
        }
        #pragma unroll
        for (int off = 1; off <= 2; off <<= 1) {
            rs0 += __shfl_xor_sync(0xffffffffu, rs0, off);
            rs1 += __shfl_xor_sync(0xffffffffu, rs1, off);
        }
        l0 = l0 * cr0 + rs0;
        l1 = l1 * cr1 + rs1;
        #pragma unroll
        for (int nt = 0; nt < 8; nt++) {
            acc[nt][0] *= cr0; acc[nt][1] *= cr0;
            acc[nt][2] *= cr1; acc[nt][3] *= cr1;
        }

        #pragma unroll
        for (int nb = 0; nb < 4; nb++) {
            #pragma unroll
            for (int kc = 0; kc < 4; kc++) {
                uint32_t vh[4], vl[4];
                uint32_t ad = kv + 16384 +
                    SWZ((kc * 16 + vRowBase) * 128 + (nb * 2 + vC) * 16);
                ldsm_x4_t(vh, ad);
                ldsm_x4_t(vl, ad + 8192);
                uint32_t ah[4] = { pah0[2*kc], pah1[2*kc], pah0[2*kc+1], pah1[2*kc+1] };
                uint32_t al[4] = { pal0[2*kc], pal1[2*kc], pal0[2*kc+1], pal1[2*kc+1] };
                mma16816(acc[nb * 2],     ah, vh);
                mma16816(acc[nb * 2],     ah, vl);
                mma16816(acc[nb * 2],     al, vh);
                mma16816(acc[nb * 2 + 1], ah, vh + 2);
                mma16816(acc[nb * 2 + 1], ah, vl + 2);
                mma16816(acc[nb * 2 + 1], al, vh + 2);
            }
        }
        __syncthreads();
    }

    const float inv0 = 1.0f / l0, inv1 = 1.0f / l1;
    const long r0 = q0 + warp * 16 + (lane >> 2);
    #pragma unroll
    for (int nt = 0; nt < 8; nt++) {
        int e = nt * 8 + (lane & 3) * 2;
        long i0 = (long)h * SQ * HDIM + r0 * HDIM + e;
        long i1 = i0 + 8L * HDIM;
        __nv_bfloat162 h2, l2;
        split2(acc[nt][0] * inv0, acc[nt][1] * inv0, h2, l2);
        *reinterpret_cast<uint32_t*>(&AOhi[i0]) = b2u(h2);
        *reinterpret_cast<uint32_t*>(&AOlo[i0]) = b2u(l2);
        split2(acc[nt][2] * inv1, acc[nt][3] * inv1, h2, l2);
        *reinterpret_cast<uint32_t*>(&AOhi[i1]) = b2u(h2);
        *reinterpret_cast<uint32_t*>(&AOlo[i1]) = b2u(l2);
    }
}

// ---------------- launch ----------------------------------------------------
extern "C" void kernel_launch(void* const* d_in, const int* in_sizes, int n_in,
                              void* d_out, int out_size) {
    const float* GLO = (const float*)d_in[0];
    const float* LOC = (const float*)d_in[1];
    const float* Wq  = (const float*)d_in[2];
    const float* Wk  = (const float*)d_in[3];
    const float* Wv  = (const float*)d_in[4];
    const float* Wo  = (const float*)d_in[5];
    float* out = (float*)d_out;

    cudaFuncSetAttribute(mma_gemm_kernel, cudaFuncAttributeMaxDynamicSharedMemorySize, SM_MMA);
    cudaFuncSetAttribute(attn_kernel, cudaFuncAttributeMaxDynamicSharedMemorySize, SMEMA);

    conv_all_kernel<<<5120, 256>>>(GLO, LOC, Wq, Wk, Wv, Wo);

    mma_gemm_kernel<<<dim3(16, 8, 6), 256, SM_MMA>>>(out, 0);   // projections
    attn_kernel<<<dim3(16, NH, 2), 256, SMEMA>>>();
    mma_gemm_kernel<<<dim3(16, 8, 2), 256, SM_MMA>>>(out, 1);   // out-proj
}

// round 17
// speedup vs baseline: 4.5475x; 1.0210x over previous
#include <cuda_runtime.h>
#include <cuda_bf16.h>
#include <cstdint>
#include <math.h>

#define SQ   2048
#define DIM  1024
#define NH   16
#define HDIM 64
#define NELEM (NH * SQ * HDIM)   // elems per [H,S,HD] tensor

// ---------------- scratch (all __device__ globals; no allocs) --------------
__device__ __nv_bfloat16 g_qkvh[6L * NELEM];           // Q,K,V hi  [z][h][s][64]
__device__ __nv_bfloat16 g_qkvl[6L * NELEM];           // Q,K,V lo
__device__ __nv_bfloat16 g_act[4L * SQ * DIM];         // Ghi,Glo,Lhi,Llo
__device__ __nv_bfloat16 g_w_hi[3L * NH * HDIM * DIM]; // [w][h][n][k]
__device__ __nv_bfloat16 g_w_lo[3L * NH * HDIM * DIM];
__device__ __nv_bfloat16 g_wo_hi[(long)DIM * DIM];     // [n][k]
__device__ __nv_bfloat16 g_wo_lo[(long)DIM * DIM];
__device__ __nv_bfloat16 g_ao[4L * SQ * DIM];          // z0hi,z0lo,z1hi,z1lo

// ---------------- mma.sync / ldmatrix / cp.async helpers -------------------
__device__ __forceinline__ uint32_t smem_u32(const void* p) {
    uint32_t a;
    asm("{ .reg .u64 t; cvta.to.shared.u64 t, %1; cvt.u32.u64 %0, t; }"
        : "=r"(a) : "l"(p));
    return a;
}
__device__ __forceinline__ void mma16816(float* d, const uint32_t* a,
                                         const uint32_t* b) {
    asm volatile(
        "mma.sync.aligned.m16n8k16.row.col.f32.bf16.bf16.f32 "
        "{%0,%1,%2,%3}, {%4,%5,%6,%7}, {%8,%9}, {%0,%1,%2,%3};"
        : "+f"(d[0]), "+f"(d[1]), "+f"(d[2]), "+f"(d[3])
        : "r"(a[0]), "r"(a[1]), "r"(a[2]), "r"(a[3]), "r"(b[0]), "r"(b[1]));
}
__device__ __forceinline__ void ldsm_x4(uint32_t* r, uint32_t addr) {
    asm volatile("ldmatrix.sync.aligned.m8n8.x4.shared.b16 {%0,%1,%2,%3}, [%4];"
        : "=r"(r[0]), "=r"(r[1]), "=r"(r[2]), "=r"(r[3]) : "r"(addr));
}
__device__ __forceinline__ void ldsm_x4_t(uint32_t* r, uint32_t addr) {
    asm volatile("ldmatrix.sync.aligned.m8n8.x4.trans.shared.b16 {%0,%1,%2,%3}, [%4];"
        : "=r"(r[0]), "=r"(r[1]), "=r"(r[2]), "=r"(r[3]) : "r"(addr));
}
#define CP_ASYNC16(s, g) \
    asm volatile("cp.async.cg.shared.global [%0], [%1], 16;" :: "r"(s), "l"(g))
#define CP_COMMIT() asm volatile("cp.async.commit_group;" ::: "memory")
#define CP_WAIT(n)  asm volatile("cp.async.wait_group %0;" :: "n"(n) : "memory")
#define SWZ(off) ((off) ^ (((off) >> 3) & 0x70))

// ---------------- bf16 hi/lo split helper ----------------------------------
__device__ __forceinline__ void split2(float a, float b,
                                       __nv_bfloat162& h2, __nv_bfloat162& l2) {
    __nv_bfloat16 ha = __float2bfloat16(a), hb = __float2bfloat16(b);
    __nv_bfloat16 la = __float2bfloat16(a - __bfloat162float(ha));
    __nv_bfloat16 lb = __float2bfloat16(b - __bfloat162float(hb));
    h2 = __nv_bfloat162(ha, hb);
    l2 = __nv_bfloat162(la, lb);
}
__device__ __forceinline__ uint32_t b2u(__nv_bfloat162 v) {
    return *reinterpret_cast<uint32_t*>(&v);
}

// ---------------- fused convert kernel (one launch) ------------------------
__global__ __launch_bounds__(256)
void conv_all_kernel(const float* __restrict__ GLO, const float* __restrict__ LOC,
                     const float* __restrict__ Wq, const float* __restrict__ Wk,
                     const float* __restrict__ Wv, const float* __restrict__ Wo) {
    __shared__ float t[64][65];
    const int b = blockIdx.x;
    const int tid = threadIdx.x;

    if (b < 4096) {
        const int y = b >> 11, x = b & 2047;
        const float* src = y ? LOC : GLO;
        __nv_bfloat16* hi = g_act + (long)(y * 2 + 0) * SQ * DIM;
        __nv_bfloat16* lo = g_act + (long)(y * 2 + 1) * SQ * DIM;
        long i = (long)x * 256 + tid;
        float4 v = reinterpret_cast<const float4*>(src)[i];
        __nv_bfloat162 h0, l0, h1, l1;
        split2(v.x, v.y, h0, l0);
        split2(v.z, v.w, h1, l1);
        reinterpret_cast<__nv_bfloat162*>(hi)[i * 2]     = h0;
        reinterpret_cast<__nv_bfloat162*>(hi)[i * 2 + 1] = h1;
        reinterpret_cast<__nv_bfloat162*>(lo)[i * 2]     = l0;
        reinterpret_cast<__nv_bfloat162*>(lo)[i * 2 + 1] = l1;
    } else if (b < 4864) {
        const int idx = b - 4096;
        const int k0 = (idx & 15) * 64, h = (idx >> 4) & 15, w = idx >> 8;
        const float* W = ((w == 0) ? Wq : (w == 1) ? Wk : Wv) + (long)h * DIM * HDIM;
        #pragma unroll
        for (int it = 0; it < 4; it++) {
            int task = tid + it * 256;
            int k = task >> 4, n4 = (task & 15) * 4;
            float4 v = *reinterpret_cast<const float4*>(&W[(long)(k0 + k) * HDIM + n4]);
            t[k][n4] = v.x; t[k][n4 + 1] = v.y; t[k][n4 + 2] = v.z; t[k][n4 + 3] = v.w;
        }
        __syncthreads();
        __nv_bfloat16* dh = g_w_hi + (long)(w * NH + h) * HDIM * DIM + k0;
        __nv_bfloat16* dl = g_w_lo + (long)(w * NH + h) * HDIM * DIM + k0;
        #pragma unroll
        for (int it = 0; it < 8; it++) {
            int task = tid + it * 256;
            int n = task >> 5, k2 = (task & 31) * 2;
            __nv_bfloat162 h2, l2;
            split2(t[k2][n], t[k2 + 1][n], h2, l2);
            *reinterpret_cast<__nv_bfloat162*>(&dh[(long)n * DIM + k2]) = h2;
            *reinterpret_cast<__nv_bfloat162*>(&dl[(long)n * DIM + k2]) = l2;
        }
    } else {
        const int idx = b - 4864;
        const int k0 = (idx & 15) * 64, n0 = (idx >> 4) * 64;
        #pragma unroll
        for (int it = 0; it < 4; it++) {
            int task = tid + it * 256;
            int k = task >> 4, n4 = (task & 15) * 4;
            float4 v = *reinterpret_cast<const float4*>(&Wo[(long)(k0 + k) * DIM + n0 + n4]);
            t[k][n4] = v.x; t[k][n4 + 1] = v.y; t[k][n4 + 2] = v.z; t[k][n4 + 3] = v.w;
        }
        __syncthreads();
        #pragma unroll
        for (int it = 0; it < 8; it++) {
            int task = tid + it * 256;
            int n = task >> 5, k2 = (task & 31) * 2;
            __nv_bfloat162 h2, l2;
            split2(t[k2][n], t[k2 + 1][n], h2, l2);
            *reinterpret_cast<__nv_bfloat162*>(&g_wo_hi[(long)(n0 + n) * DIM + k0 + k2]) = h2;
            *reinterpret_cast<__nv_bfloat162*>(&g_wo_lo[(long)(n0 + n) * DIM + k0 + k2]) = l2;
        }
    }
}

// ---------------- mma.sync bf16-split GEMM ---------------------------------
// 256 thr = 8 warps in 2x4 grid, 64m x 32n per warp (LDSM:MMA = 1:4).
// 3-stage cp.async ring, ONE __syncthreads per chunk.
// Stage layout: [Ahi 128x80][Bhi 128x80][Alo 128x64 swz][Blo 128x64 swz].
#define AHI_OFF 0
#define BHI_OFF 10240
#define ALO_OFF 20480
#define BLO_OFF 28672
#define STG_B   36864
#define SM_MMA  (3 * STG_B)   // 110592 -> 2 CTAs/SM

__global__ __launch_bounds__(256, 2)
void mma_gemm_kernel(float* __restrict__ Cout, int mode) {
    extern __shared__ char smc[];
    const uint32_t sb = smem_u32(smc);
    const int tid = threadIdx.x;
    const int wid = tid >> 5, lane = tid & 31;
    const int wr = wid >> 2, wc = wid & 3;       // 2x4 warp grid (64m x 32n)
    const int m0 = blockIdx.x * 128;

    const __nv_bfloat16 *Ahi, *Alo, *Bhi, *Blo;
    float *C0f = nullptr, *C1f = nullptr;
    __nv_bfloat16 *C0h = nullptr, *C1h = nullptr, *C0l = nullptr, *C1l = nullptr;
    if (mode == 0) {
        const int z = blockIdx.z, hp = blockIdx.y;
        const int act = (z < 3) ? 0 : 1, w = (z < 3) ? z : z - 3;
        Ahi = g_act + (long)(act * 2 + 0) * SQ * DIM;
        Alo = g_act + (long)(act * 2 + 1) * SQ * DIM;
        Bhi = g_w_hi + (long)(w * NH + hp * 2) * HDIM * DIM;
        Blo = g_w_lo + (long)(w * NH + hp * 2) * HDIM * DIM;
        long coff = (long)z * NELEM + (long)(hp * 2) * SQ * HDIM + (long)m0 * HDIM;
        C0h = g_qkvh + coff; C1h = C0h + (long)SQ * HDIM;
        C0l = g_qkvl + coff; C1l = C0l + (long)SQ * HDIM;
    } else {
        const int z = blockIdx.z, n0 = blockIdx.y * 128;
        Ahi = g_ao + (long)(z * 2 + 0) * SQ * DIM;
        Alo = g_ao + (long)(z * 2 + 1) * SQ * DIM;
        Bhi = g_wo_hi + (long)n0 * DIM;
        Blo = g_wo_lo + (long)n0 * DIM;
        C0f = Cout + (long)z * SQ * DIM + (long)m0 * DIM + n0;
        C1f = C0f + 64;
    }

    const char* Ah = (const char*)(Ahi + (long)m0 * DIM);
    const char* Al = (const char*)(Alo + (long)m0 * DIM);
    const char* Bh = (const char*)Bhi;
    const char* Bl = (const char*)Blo;

    auto issue_chunk = [&](int chunk, uint32_t stg) {
        const long go = (long)chunk * 64;   // 32 k-elems = 64 bytes
        #pragma unroll
        for (int it = 0; it < 2; it++) {
            int task = tid + it * 256;
            int r = task >> 2, cq = task & 3;
            int cb = cq * 16;
            int cs = ((cq ^ (r & 3)) << 4);   // lo-tensor XOR swizzle
            CP_ASYNC16(stg + AHI_OFF + r * 80 + cb, Ah + (long)r * 2048 + go + cb);
            CP_ASYNC16(stg + BHI_OFF + r * 80 + cb, Bh + (long)r * 2048 + go + cb);
            CP_ASYNC16(stg + ALO_OFF + r * 64 + cs, Al + (long)r * 2048 + go + cb);
            CP_ASYNC16(stg + BLO_OFF + r * 64 + cs, Bl + (long)r * 2048 + go + cb);
        }
    };

    // prologue: chunks 0,1 into stages 0,1
    issue_chunk(0, sb);
    CP_COMMIT();
    issue_chunk(1, sb + STG_B);
    CP_COMMIT();

    const int aRow  = wr * 64 + (lane & 7) + ((lane >> 3) & 1) * 8;
    const int aHalf = lane >> 4;
    const int bRow  = wc * 32 + (lane & 7) + ((lane >> 4) & 1) * 8;
    const int bHalf = (lane >> 3) & 1;
    const int aSw   = aRow & 3;
    const int bSw   = bRow & 3;

    float acc[4][4][4] = {};   // [mtile(16)][ntile(8)][frag]

    int sRead = 0, sWrite = 2;
    for (int c = 0; c < 32; c++) {
        if (c < 31) { CP_WAIT(1); } else { CP_WAIT(0); }
        __syncthreads();   // stage sRead visible; stage sWrite's readers done
        if (c + 2 < 32) {
            issue_chunk(c + 2, sb + sWrite * STG_B);
            CP_COMMIT();
        }

        const uint32_t st = sb + sRead * STG_B;
        #pragma unroll
        for (int ks = 0; ks < 2; ks++) {
            uint32_t ah[4][4], al[4][4];
            const int caLo = ((ks * 2 + aHalf) ^ aSw) << 4;
            #pragma unroll
            for (int mt = 0; mt < 4; mt++) {
                ldsm_x4(ah[mt], st + AHI_OFF + (aRow + mt * 16) * 80 + ks * 32 + aHalf * 16);
                ldsm_x4(al[mt], st + ALO_OFF + (aRow + mt * 16) * 64 + caLo);
            }
            const int cbLo = ((ks * 2 + bHalf) ^ bSw) << 4;
            #pragma unroll
            for (int np = 0; np < 2; np++) {
                uint32_t bh[4], bl[4];
                ldsm_x4(bh, st + BHI_OFF + (bRow + np * 16) * 80 + ks * 32 + bHalf * 16);
                ldsm_x4(bl, st + BLO_OFF + (bRow + np * 16) * 64 + cbLo);
                // term-major order: consecutive MMAs hit different accumulators
                #pragma unroll
                for (int mt = 0; mt < 4; mt++)
                    #pragma unroll
                    for (int ntl = 0; ntl < 2; ntl++)
                        mma16816(acc[mt][np * 2 + ntl], ah[mt], bh + ntl * 2);
                #pragma unroll
                for (int mt = 0; mt < 4; mt++)
                    #pragma unroll
                    for (int ntl = 0; ntl < 2; ntl++)
                        mma16816(acc[mt][np * 2 + ntl], ah[mt], bl + ntl * 2);
                #pragma unroll
                for (int mt = 0; mt < 4; mt++)
                    #pragma unroll
                    for (int ntl = 0; ntl < 2; ntl++)
                        mma16816(acc[mt][np * 2 + ntl], al[mt], bh + ntl * 2);
            }
        }
        sRead  = (sRead  == 2) ? 0 : sRead + 1;
        sWrite = (sWrite == 2) ? 0 : sWrite + 1;
    }

    const int rrel = wr * 64 + (lane >> 2);
    #pragma unroll
    for (int mt = 0; mt < 4; mt++)
        #pragma unroll
        for (int nt = 0; nt < 4; nt++) {
            int ncol = wc * 32 + nt * 8 + (lane & 3) * 2;
            int col = ncol & 63;
            long r0 = rrel + mt * 16, r1 = r0 + 8;
            if (mode == 0) {
                __nv_bfloat16* Ph = (ncol >= 64) ? C1h : C0h;
                __nv_bfloat16* Pl = (ncol >= 64) ? C1l : C0l;
                __nv_bfloat162 h2, l2;
                split2(acc[mt][nt][0], acc[mt][nt][1], h2, l2);
                *reinterpret_cast<uint32_t*>(&Ph[r0 * 64 + col]) = b2u(h2);
                *reinterpret_cast<uint32_t*>(&Pl[r0 * 64 + col]) = b2u(l2);
                split2(acc[mt][nt][2], acc[mt][nt][3], h2, l2);
                *reinterpret_cast<uint32_t*>(&Ph[r1 * 64 + col]) = b2u(h2);
                *reinterpret_cast<uint32_t*>(&Pl[r1 * 64 + col]) = b2u(l2);
            } else {
                float* P = (ncol >= 64) ? C1f : C0f;
                *reinterpret_cast<float2*>(&P[r0 * DIM + col]) =
                    make_float2(acc[mt][nt][0], acc[mt][nt][1]);
                *reinterpret_cast<float2*>(&P[r1 * DIM + col]) =
                    make_float2(acc[mt][nt][2], acc[mt][nt][3]);
            }
        }
}

// ---------------- mma.sync flash attention (unchanged) ---------------------
#define AT_Q   0
#define AT_KV  32768
#define AT_STG 32768
#define SMEMA  (32768 + 2 * 32768)   // 98304

__global__ __launch_bounds__(256, 2)
void attn_kernel() {
    extern __shared__ char sma[];
    const uint32_t sb = smem_u32(sma);
    const int tid = threadIdx.x, lane = tid & 31, warp = tid >> 5;
    const int z = blockIdx.z, h = blockIdx.y, q0 = blockIdx.x * 128;

    const long hoff = (long)h * SQ * HDIM;
    const __nv_bfloat16* Qh_ = g_qkvh + (long)(z ? 3 : 0) * NELEM + hoff;
    const __nv_bfloat16* Ql_ = g_qkvl + (long)(z ? 3 : 0) * NELEM + hoff;
    const __nv_bfloat16* Kh_ = g_qkvh + (long)(z ? 1 : 4) * NELEM + hoff;
    const __nv_bfloat16* Kl_ = g_qkvl + (long)(z ? 1 : 4) * NELEM + hoff;
    const __nv_bfloat16* Vh_ = g_qkvh + (long)(z ? 2 : 5) * NELEM + hoff;
    const __nv_bfloat16* Vl_ = g_qkvl + (long)(z ? 2 : 5) * NELEM + hoff;
    __nv_bfloat16* AOhi = g_ao + (long)(z * 2 + 0) * SQ * DIM;
    __nv_bfloat16* AOlo = g_ao + (long)(z * 2 + 1) * SQ * DIM;

    #pragma unroll
    for (int it = 0; it < 4; it++) {
        int task = tid + it * 256;
        int r = task >> 3, c = task & 7;
        uint32_t d = SWZ(r * 128 + c * 16);
        CP_ASYNC16(sb + AT_Q + d,         (const char*)(Qh_ + (long)(q0 + r) * 64) + c * 16);
        CP_ASYNC16(sb + AT_Q + 16384 + d, (const char*)(Ql_ + (long)(q0 + r) * 64) + c * 16);
    }
    #pragma unroll
    for (int it = 0; it < 2; it++) {
        int task = tid + it * 256;
        int r = task >> 3, c = task & 7;
        uint32_t d = SWZ(r * 128 + c * 16);
        const long g = (long)r * 64;
        CP_ASYNC16(sb + AT_KV + 0     + d, (const char*)(Kh_ + g) + c * 16);
        CP_ASYNC16(sb + AT_KV + 8192  + d, (const char*)(Kl_ + g) + c * 16);
        CP_ASYNC16(sb + AT_KV + 16384 + d, (const char*)(Vh_ + g) + c * 16);
        CP_ASYNC16(sb + AT_KV + 24576 + d, (const char*)(Vl_ + g) + c * 16);
    }
    CP_COMMIT();

    float acc[8][4] = {};
    float m0 = -1e30f, m1 = -1e30f, l0 = 0.f, l1 = 0.f;
    const float scale = 0.125f;

    const int aRow = warp * 16 + (lane & 7) + ((lane >> 3) & 1) * 8;
    const int aC   = lane >> 4;
    const int kRowBase = (lane & 7) + ((lane >> 4) & 1) * 8;
    const int kC   = (lane >> 3) & 1;
    const int vRowBase = (lane & 7) + ((lane >> 3) & 1) * 8;
    const int vC   = lane >> 4;

    for (int j = 0; j < 32; j++) {
        if (j + 1 < 32) {
            const uint32_t so = sb + AT_KV + ((j + 1) & 1) * AT_STG;
            const long j1 = (long)(j + 1) * 64;
            #pragma unroll
            for (int it = 0; it < 2; it++) {
                int task = tid + it * 256;
                int r = task >> 3, c = task & 7;
                uint32_t d = SWZ(r * 128 + c * 16);
                const long g = (j1 + r) * 64;
                CP_ASYNC16(so + 0     + d, (const char*)(Kh_ + g) + c * 16);
                CP_ASYNC16(so + 8192  + d, (const char*)(Kl_ + g) + c * 16);
                CP_ASYNC16(so + 16384 + d, (const char*)(Vh_ + g) + c * 16);
                CP_ASYNC16(so + 24576 + d, (const char*)(Vl_ + g) + c * 16);
            }
            CP_COMMIT();
            CP_WAIT(1);
        } else {
            CP_WAIT(0);
        }
        __syncthreads();

        const uint32_t kv = sb + AT_KV + (j & 1) * AT_STG;

        uint32_t qh[4][4], ql[4][4];
        #pragma unroll
        for (int kc = 0; kc < 4; kc++) {
            uint32_t ad = sb + AT_Q + SWZ(aRow * 128 + (kc * 2 + aC) * 16);
            ldsm_x4(qh[kc], ad);
            ldsm_x4(ql[kc], ad + 16384);
        }

        float s[8][4] = {};
        #pragma unroll
        for (int nb = 0; nb < 4; nb++) {
            #pragma unroll
            for (int kc = 0; kc < 4; kc++) {
                uint32_t kh[4], kl[4];
                uint32_t ad = kv + SWZ((nb * 16 + kRowBase) * 128 + (kc * 2 + kC) * 16);
                ldsm_x4(kh, ad);
                ldsm_x4(kl, ad + 8192);
                mma16816(s[nb * 2],     qh[kc], kh);
                mma16816(s[nb * 2 + 1], qh[kc], kh + 2);
                mma16816(s[nb * 2],     qh[kc], kl);
                mma16816(s[nb * 2 + 1], qh[kc], kl + 2);
                mma16816(s[nb * 2],     ql[kc], kh);
                mma16816(s[nb * 2 + 1], ql[kc], kh + 2);
            }
        }

        float mx0 = -1e30f, mx1 = -1e30f;
        #pragma unroll
        for (int nt = 0; nt < 8; nt++) {
            mx0 = fmaxf(mx0, fmaxf(s[nt][0], s[nt][1]));
            mx1 = fmaxf(mx1, fmaxf(s[nt][2], s[nt][3]));
        }
        #pragma unroll
        for (int off = 1; off <= 2; off <<= 1) {
            mx0 = fmaxf(mx0, __shfl_xor_sync(0xffffffffu, mx0, off));
            mx1 = fmaxf(mx1, __shfl_xor_sync(0xffffffffu, mx1, off));
        }
        float nm0 = fmaxf(m0, mx0 * scale), nm1 = fmaxf(m1, mx1 * scale);
        float cr0 = __expf(m0 - nm0), cr1 = __expf(m1 - nm1);
        m0 = nm0; m1 = nm1;

        uint32_t pah0[8], pal0[8], pah1[8], pal1[8];
        float rs0 = 0.f, rs1 = 0.f;
        #pragma unroll
        for (int nt = 0; nt < 8; nt++) {
            float p0 = __expf(s[nt][0] * scale - m0);
            float p1 = __expf(s[nt][1] * scale - m0);
            float p2 = __expf(s[nt][2] * scale - m1);
            float p3 = __expf(s[nt][3] * scale - m1);
            rs0 += p0 + p1; rs1 += p2 + p3;
            __nv_bfloat162 h2, l2;
            split2(p0, p1, h2, l2);
            pah0[nt] = b2u(h2); pal0[nt] = b2u(l2);
            split2(p2, p3, h2, l2);
            pah1[nt] = b2u(h2); pal1[nt] = b2u(l2);
        }
        #pragma unroll
        for (int off = 1; off <= 2; off <<= 1) {
            rs0 += __shfl_xor_sync(0xffffffffu, rs0, off);
            rs1 += __shfl_xor_sync(0xffffffffu, rs1, off);
        }
        l0 = l0 * cr0 + rs0;
        l1 = l1 * cr1 + rs1;
        #pragma unroll
        for (int nt = 0; nt < 8; nt++) {
            acc[nt][0] *= cr0; acc[nt][1] *= cr0;
            acc[nt][2] *= cr1; acc[nt][3] *= cr1;
        }

        #pragma unroll
        for (int nb = 0; nb < 4; nb++) {
            #pragma unroll
            for (int kc = 0; kc < 4; kc++) {
                uint32_t vh[4], vl[4];
                uint32_t ad = kv + 16384 +
                    SWZ((kc * 16 + vRowBase) * 128 + (nb * 2 + vC) * 16);
                ldsm_x4_t(vh, ad);
                ldsm_x4_t(vl, ad + 8192);
                uint32_t ah[4] = { pah0[2*kc], pah1[2*kc], pah0[2*kc+1], pah1[2*kc+1] };
                uint32_t al[4] = { pal0[2*kc], pal1[2*kc], pal0[2*kc+1], pal1[2*kc+1] };
                mma16816(acc[nb * 2],     ah, vh);
                mma16816(acc[nb * 2 + 1], ah, vh + 2);
                mma16816(acc[nb * 2],     ah, vl);
                mma16816(acc[nb * 2 + 1], ah, vl + 2);
                mma16816(acc[nb * 2],     al, vh);
                mma16816(acc[nb * 2 + 1], al, vh + 2);
            }
        }
        __syncthreads();
    }

    const float inv0 = 1.0f / l0, inv1 = 1.0f / l1;
    const long r0 = q0 + warp * 16 + (lane >> 2);
    #pragma unroll
    for (int nt = 0; nt < 8; nt++) {
        int e = nt * 8 + (lane & 3) * 2;
        long i0 = (long)h * SQ * HDIM + r0 * HDIM + e;
        long i1 = i0 + 8L * HDIM;
        __nv_bfloat162 h2, l2;
        split2(acc[nt][0] * inv0, acc[nt][1] * inv0, h2, l2);
        *reinterpret_cast<uint32_t*>(&AOhi[i0]) = b2u(h2);
        *reinterpret_cast<uint32_t*>(&AOlo[i0]) = b2u(l2);
        split2(acc[nt][2] * inv1, acc[nt][3] * inv1, h2, l2);
        *reinterpret_cast<uint32_t*>(&AOhi[i1]) = b2u(h2);
        *reinterpret_cast<uint32_t*>(&AOlo[i1]) = b2u(l2);
    }
}

// ---------------- launch ----------------------------------------------------
extern "C" void kernel_launch(void* const* d_in, const int* in_sizes, int n_in,
                              void* d_out, int out_size) {
    const float* GLO = (const float*)d_in[0];
    const float* LOC = (const float*)d_in[1];
    const float* Wq  = (const float*)d_in[2];
    const float* Wk  = (const float*)d_in[3];
    const float* Wv  = (const float*)d_in[4];
    const float* Wo  = (const float*)d_in[5];
    float* out = (float*)d_out;

    cudaFuncSetAttribute(mma_gemm_kernel, cudaFuncAttributeMaxDynamicSharedMemorySize, SM_MMA);
    cudaFuncSetAttribute(attn_kernel, cudaFuncAttributeMaxDynamicSharedMemorySize, SMEMA);

    conv_all_kernel<<<5120, 256>>>(GLO, LOC, Wq, Wk, Wv, Wo);

    mma_gemm_kernel<<<dim3(16, 8, 6), 256, SM_MMA>>>(out, 0);   // projections
    attn_kernel<<<dim3(16, NH, 2), 256, SMEMA>>>();
    mma_gemm_kernel<<<dim3(16, 8, 2), 256, SM_MMA>>>(out, 1);   // out-proj
}